// round 10
// baseline (speedup 1.0000x reference)
#include <cuda_runtime.h>
#include <cuda_bf16.h>
#include <math.h>
#include <stdint.h>

#define Bsz   2
#define Lseq  2048
#define Dmod  1024
#define Hh    16
#define HD    64
#define MROWS 4096
#define BH    32
#define OUT_ELEMS  (MROWS * Dmod)
#define BIAS_ELEMS (Hh * Lseq * Lseq)
#define LOG2E 1.4426950408889634f

typedef __nv_bfloat16 bf16;

// ---------------- scratch ----------------
__device__ bf16 g_Xhi[MROWS * Dmod], g_Xlo[MROWS * Dmod];
__device__ bf16 g_Whi[4 * Dmod * Dmod], g_Wlo[4 * Dmod * Dmod];
__device__ bf16 g_Qhi[BH * Lseq * HD], g_Qlo[BH * Lseq * HD];
__device__ bf16 g_Khi[BH * Lseq * HD], g_Klo[BH * Lseq * HD];
__device__ bf16 g_Vthi[BH * HD * Lseq], g_Vtlo[BH * HD * Lseq];
__device__ bf16 g_Chi[MROWS * Dmod], g_Clo[MROWS * Dmod];
__device__ float g_F[MROWS * Dmod];
__device__ float g_HL[Hh * 4095];
__device__ float g_O[OUT_ELEMS];

// ============================================================
// helpers
// ============================================================
__device__ __forceinline__ uint32_t smem_u32(const void* p) {
    uint32_t a;
    asm("{ .reg .u64 t; cvta.to.shared.u64 t, %1; cvt.u32.u64 %0, t; }" : "=r"(a) : "l"(p));
    return a;
}
__device__ __forceinline__ void ldsm4(uint32_t* r, uint32_t addr) {
    asm volatile("ldmatrix.sync.aligned.m8n8.x4.shared.b16 {%0,%1,%2,%3}, [%4];"
        : "=r"(r[0]), "=r"(r[1]), "=r"(r[2]), "=r"(r[3]) : "r"(addr));
}
__device__ __forceinline__ void mma_bf16(float* c, const uint32_t* a, const uint32_t* b) {
    asm volatile(
        "mma.sync.aligned.m16n8k16.row.col.f32.bf16.bf16.f32 "
        "{%0,%1,%2,%3}, {%4,%5,%6,%7}, {%8,%9}, {%0,%1,%2,%3};"
        : "+f"(c[0]), "+f"(c[1]), "+f"(c[2]), "+f"(c[3])
        : "r"(a[0]), "r"(a[1]), "r"(a[2]), "r"(a[3]), "r"(b[0]), "r"(b[1]));
}
__device__ __forceinline__ uint32_t packsplit(float x, float y, uint32_t& lo) {
    __nv_bfloat162 h = __floats2bfloat162_rn(x, y);
    float hx = __bfloat162float(h.x), hy = __bfloat162float(h.y);
    __nv_bfloat162 l = __floats2bfloat162_rn(x - hx, y - hy);
    lo = *(uint32_t*)&l;
    return *(uint32_t*)&h;
}
__device__ __forceinline__ void cpa16(uint32_t s, const void* g) {
    asm volatile("cp.async.cg.shared.global [%0], [%1], 16;" :: "r"(s), "l"(g) : "memory");
}
__device__ __forceinline__ void cpa_commit() { asm volatile("cp.async.commit_group;" ::: "memory"); }
__device__ __forceinline__ void cpa_wait1()  { asm volatile("cp.async.wait_group 1;" ::: "memory"); }
__device__ __forceinline__ void cpa_wait0()  { asm volatile("cp.async.wait_group 0;" ::: "memory"); }

// ============================================================
// T5 bias LUT + bias fill (verified)
// ============================================================
__global__ void build_headlut_kernel(const float* __restrict__ bt, float* __restrict__ hl)
{
    int idx = blockIdx.x * blockDim.x + threadIdx.x;
    if (idx >= Hh * 4095) return;
    int h = idx / 4095;
    int t = idx - h * 4095;
    int rel = t - 2047;
    int bucket = (rel > 0) ? 16 : 0;
    int rp = rel < 0 ? -rel : rel;
    int add;
    if (rp < 8) {
        add = rp;
    } else {
        float v = (logf((float)rp * 0.125f) / 2.772588722239781f) * 8.0f;
        int lv = 8 + (int)v;
        if (rp == 16) lv = 10;
        else if (rp == 32) lv = 12;
        else if (rp == 64) lv = 14;
        add = lv > 15 ? 15 : lv;
    }
    bucket += add;
    hl[idx] = bt[bucket * Hh + h];
}

__global__ void fill_bias_kernel(const float* __restrict__ hl, float* __restrict__ pb)
{
    int i = blockIdx.x;
    int h = blockIdx.y;
    const float* src = hl + h * 4095 + (2047 - i);
    float4* dst = (float4*)(pb + ((size_t)(h * Lseq + i)) * Lseq);
    int j = threadIdx.x * 4;
    dst[threadIdx.x] = make_float4(src[j], src[j + 1], src[j + 2], src[j + 3]);
}

// ============================================================
// split / pack
// ============================================================
__device__ __forceinline__ void split1(float x, bf16& h, bf16& l) {
    h = __float2bfloat16(x);
    l = __float2bfloat16(x - __bfloat162float(h));
}

__global__ void split_kernel(const float* __restrict__ s, bf16* __restrict__ hi,
                             bf16* __restrict__ lo, int n)
{
    int i = blockIdx.x * 256 + threadIdx.x;
    if (i >= n) return;
    split1(s[i], hi[i], lo[i]);
}

__global__ void splitW_kernel(const float* __restrict__ W0, const float* __restrict__ W1,
                              const float* __restrict__ W2, const float* __restrict__ W3,
                              bf16* __restrict__ hi, bf16* __restrict__ lo)
{
    int z = blockIdx.z;
    const float* s = (z == 0) ? W0 : (z == 1) ? W1 : (z == 2) ? W2 : W3;
    int i = blockIdx.x * 256 + threadIdx.x;
    size_t o = (size_t)z * (Dmod * Dmod) + i;
    split1(s[i], hi[o], lo[o]);
}

__global__ void v_packT_kernel(const float* __restrict__ F, bf16* __restrict__ hi,
                               bf16* __restrict__ lo)
{
    __shared__ float t[32][33];
    int bh = blockIdx.z, b = bh >> 4, h = bh & 15;
    int l0 = blockIdx.x * 32, d0 = blockIdx.y * 32;
    int tx = threadIdx.x, ty = threadIdx.y;
#pragma unroll
    for (int r = 0; r < 4; ++r) {
        int l = l0 + ty + r * 8;
        t[ty + r * 8][tx] = F[((size_t)(b * Lseq + l)) * Dmod + h * HD + d0 + tx];
    }
    __syncthreads();
#pragma unroll
    for (int r = 0; r < 4; ++r) {
        int d = d0 + ty + r * 8;
        int l = l0 + tx;
        size_t o = ((size_t)bh * HD + d) * Lseq + l;
        split1(t[tx][ty + r * 8], hi[o], lo[o]);
    }
}

// ============================================================
// 128-thread split-bf16 HMMA GEMM, cp.async double-buffered.
// CTA tile 128x128, 4 warps, warp tile 64x64, term-major MMA order.
// ============================================================
#define PITCH 40
#define TILEB (128 * PITCH * 2)
#define GEMM_SMEM (2 * 4 * TILEB)

__device__ __forceinline__ void hg_mainloop(
    const bf16* __restrict__ Abh, const bf16* __restrict__ Abl,
    const bf16* __restrict__ Bbh, const bf16* __restrict__ Bbl,
    float c[4][8][4], char* smraw)
{
    int tid = threadIdx.x, lane = tid & 31, wid = tid >> 5;
    int wm = wid >> 1, wn = wid & 1;
    uint32_t sb = smem_u32(smraw);

    int lrow = tid >> 2, lseg = tid & 3;

    uint32_t aOff[4], bOff[4];
#pragma unroll
    for (int im = 0; im < 4; ++im)
        aOff[im] = (uint32_t)(((wm * 64 + im * 16 + (lane & 15)) * PITCH + ((lane >> 4) << 3)) * 2);
    int kq = (lane & 8) ? 8 : 0;
#pragma unroll
    for (int p = 0; p < 4; ++p)
        bOff[p] = (uint32_t)(((wn * 64 + p * 16 + ((lane & 16) >> 1) + (lane & 7)) * PITCH + kq) * 2);

    // prologue: chunk 0 -> stage 0
#pragma unroll
    for (int v = 0; v < 4; ++v) {
        int row = lrow + v * 32;
        uint32_t st = sb + (uint32_t)(row * PITCH * 2 + lseg * 16);
        size_t goff = (size_t)row * Dmod + lseg * 8;
        cpa16(st,             Abh + goff);
        cpa16(st + TILEB,     Abl + goff);
        cpa16(st + 2 * TILEB, Bbh + goff);
        cpa16(st + 3 * TILEB, Bbl + goff);
    }
    cpa_commit();

    for (int kc = 0; kc < 32; ++kc) {
        if (kc < 31) {
            int k0 = (kc + 1) << 5;
            uint32_t stg = sb + ((kc + 1) & 1) * (4 * TILEB);
#pragma unroll
            for (int v = 0; v < 4; ++v) {
                int row = lrow + v * 32;
                uint32_t st = stg + (uint32_t)(row * PITCH * 2 + lseg * 16);
                size_t goff = (size_t)row * Dmod + k0 + lseg * 8;
                cpa16(st,             Abh + goff);
                cpa16(st + TILEB,     Abl + goff);
                cpa16(st + 2 * TILEB, Bbh + goff);
                cpa16(st + 3 * TILEB, Bbl + goff);
            }
            cpa_commit();
            cpa_wait1();
        } else {
            cpa_wait0();
        }
        __syncthreads();

        uint32_t stg = sb + (kc & 1) * (4 * TILEB);
#pragma unroll
        for (int ks = 0; ks < 32; ks += 16) {
            uint32_t aH[4][4], aL[4][4];
#pragma unroll
            for (int im = 0; im < 4; ++im) {
                ldsm4(aH[im], stg + aOff[im] + ks * 2);
                ldsm4(aL[im], stg + TILEB + aOff[im] + ks * 2);
            }
#pragma unroll
            for (int ph = 0; ph < 2; ++ph) {
                uint32_t bH[2][4], bL[2][4];
#pragma unroll
                for (int pp = 0; pp < 2; ++pp) {
                    int p = ph * 2 + pp;
                    ldsm4(bH[pp], stg + 2 * TILEB + bOff[p] + ks * 2);
                    ldsm4(bL[pp], stg + 3 * TILEB + bOff[p] + ks * 2);
                }
                // term-major: 16 independent MMAs per term
#pragma unroll
                for (int im = 0; im < 4; ++im)
#pragma unroll
                    for (int pp = 0; pp < 2; ++pp)
#pragma unroll
                        for (int nfl = 0; nfl < 2; ++nfl)
                            mma_bf16(c[im][ph * 4 + pp * 2 + nfl], aH[im], &bH[pp][nfl * 2]);
#pragma unroll
                for (int im = 0; im < 4; ++im)
#pragma unroll
                    for (int pp = 0; pp < 2; ++pp)
#pragma unroll
                        for (int nfl = 0; nfl < 2; ++nfl)
                            mma_bf16(c[im][ph * 4 + pp * 2 + nfl], aH[im], &bL[pp][nfl * 2]);
#pragma unroll
                for (int im = 0; im < 4; ++im)
#pragma unroll
                    for (int pp = 0; pp < 2; ++pp)
#pragma unroll
                        for (int nfl = 0; nfl < 2; ++nfl)
                            mma_bf16(c[im][ph * 4 + pp * 2 + nfl], aL[im], &bH[pp][nfl * 2]);
            }
        }
        __syncthreads();
    }
}

__global__ void __launch_bounds__(128, 2) qkv_kernel(
    const bf16* __restrict__ Xhi, const bf16* __restrict__ Xlo,
    const bf16* __restrict__ Whi, const bf16* __restrict__ Wlo,
    bf16* __restrict__ Qhi, bf16* __restrict__ Qlo,
    bf16* __restrict__ Khi, bf16* __restrict__ Klo,
    float* __restrict__ F)
{
    extern __shared__ char smraw[];
    int z = blockIdx.z;
    int m0 = blockIdx.y << 7, n0 = blockIdx.x << 7;
    const size_t WSZ = (size_t)Dmod * Dmod;
    const bf16* Abh = Xhi + (size_t)m0 * Dmod;
    const bf16* Abl = Xlo + (size_t)m0 * Dmod;
    const bf16* Bbh = Whi + (size_t)z * WSZ + (size_t)n0 * Dmod;
    const bf16* Bbl = Wlo + (size_t)z * WSZ + (size_t)n0 * Dmod;

    float c[4][8][4];
#pragma unroll
    for (int im = 0; im < 4; ++im)
#pragma unroll
        for (int nf = 0; nf < 8; ++nf)
#pragma unroll
            for (int e = 0; e < 4; ++e) c[im][nf][e] = 0.f;

    hg_mainloop(Abh, Abl, Bbh, Bbl, c, smraw);

    int lane = threadIdx.x & 31, wid = threadIdx.x >> 5;
    int wm = wid >> 1, wn = wid & 1;
    bf16* Dhi = (z == 0) ? Qhi : Khi;
    bf16* Dlo = (z == 0) ? Qlo : Klo;

#pragma unroll
    for (int im = 0; im < 4; ++im) {
#pragma unroll
        for (int nf = 0; nf < 8; ++nf) {
            int row = m0 + wm * 64 + im * 16 + (lane >> 2);
            int col = n0 + wn * 64 + nf * 8 + 2 * (lane & 3);
            if (z == 2) {
                *(float2*)(F + (size_t)row * Dmod + col)       = make_float2(c[im][nf][0], c[im][nf][1]);
                *(float2*)(F + (size_t)(row + 8) * Dmod + col) = make_float2(c[im][nf][2], c[im][nf][3]);
            } else {
                int b = row >> 11, h = col >> 6, d = col & 63;
                size_t o0 = (((size_t)(b * Hh + h)) * Lseq + (row & 2047)) * HD + d;
                size_t o1 = o0 + 8 * HD;
                uint32_t lo0, lo1;
                uint32_t hi0 = packsplit(c[im][nf][0], c[im][nf][1], lo0);
                uint32_t hi1 = packsplit(c[im][nf][2], c[im][nf][3], lo1);
                *(uint32_t*)(Dhi + o0) = hi0;
                *(uint32_t*)(Dlo + o0) = lo0;
                *(uint32_t*)(Dhi + o1) = hi1;
                *(uint32_t*)(Dlo + o1) = lo1;
            }
        }
    }
}

__global__ void __launch_bounds__(128, 2) out_kernel(
    const bf16* __restrict__ Chi, const bf16* __restrict__ Clo,
    const bf16* __restrict__ Whi, const bf16* __restrict__ Wlo,
    float* __restrict__ outF)
{
    extern __shared__ char smraw[];
    int m0 = blockIdx.y << 7, n0 = blockIdx.x << 7;
    const bf16* Abh = Chi + (size_t)m0 * Dmod;
    const bf16* Abl = Clo + (size_t)m0 * Dmod;
    const bf16* Bbh = Whi + (size_t)n0 * Dmod;
    const bf16* Bbl = Wlo + (size_t)n0 * Dmod;

    float c[4][8][4];
#pragma unroll
    for (int im = 0; im < 4; ++im)
#pragma unroll
        for (int nf = 0; nf < 8; ++nf)
#pragma unroll
            for (int e = 0; e < 4; ++e) c[im][nf][e] = 0.f;

    hg_mainloop(Abh, Abl, Bbh, Bbl, c, smraw);

    int lane = threadIdx.x & 31, wid = threadIdx.x >> 5;
    int wm = wid >> 1, wn = wid & 1;
#pragma unroll
    for (int im = 0; im < 4; ++im) {
#pragma unroll
        for (int nf = 0; nf < 8; ++nf) {
            int row = m0 + wm * 64 + im * 16 + (lane >> 2);
            int col = n0 + wn * 64 + nf * 8 + 2 * (lane & 3);
            *(float2*)(outF + (size_t)row * Dmod + col)       = make_float2(c[im][nf][0], c[im][nf][1]);
            *(float2*)(outF + (size_t)(row + 8) * Dmod + col) = make_float2(c[im][nf][2], c[im][nf][3]);
        }
    }
}

// ============================================================
// Flash attention (term-major PV ordering; otherwise as R8/R9)
// ============================================================
#define QP 72
#define VP 136
#define KTILE (128 * QP * 2)
#define VTILE (64 * VP * 2)
#define F_QH 0
#define F_QL (F_QH + KTILE)
#define F_K  (F_QL + KTILE)
#define F_V  (F_K + 2 * 2 * KTILE)
#define F_WIN (F_V + 2 * 2 * VTILE)
#define F_PM  (F_WIN + 2048)
#define F_PS  (F_PM + 2048)
#define F_M   (F_PS + 2048)
#define F_L   (F_M + 512)
#define F_AL  (F_L + 512)
#define FLASH_SMEM (F_AL + 512)

__global__ void __launch_bounds__(512, 1) flash_kernel(
    const bf16* __restrict__ Qhi, const bf16* __restrict__ Qlo,
    const bf16* __restrict__ Khi, const bf16* __restrict__ Klo,
    const bf16* __restrict__ Vthi, const bf16* __restrict__ Vtlo,
    const float* __restrict__ hl,
    bf16* __restrict__ Chi, bf16* __restrict__ Clo)
{
    extern __shared__ char smc[];
    bf16* sQh = (bf16*)(smc + F_QH);
    bf16* sQl = (bf16*)(smc + F_QL);
    float* win = (float*)(smc + F_WIN);
    float* pm  = (float*)(smc + F_PM);
    float* ps  = (float*)(smc + F_PS);
    float* smM = (float*)(smc + F_M);
    float* smL = (float*)(smc + F_L);
    float* smA = (float*)(smc + F_AL);
    float* obuf = (float*)(smc + F_K);

    int tid = threadIdx.x, lane = tid & 31, wid = tid >> 5;
    int wm = wid >> 2, wn = wid & 3;
    int q0 = blockIdx.x << 7;
    int bh = blockIdx.y;
    int h = bh & 15, b = bh >> 4;
    const bf16* Qbh = Qhi + (size_t)bh * Lseq * HD;
    const bf16* Qbl = Qlo + (size_t)bh * Lseq * HD;
    const bf16* Kbh = Khi + (size_t)bh * Lseq * HD;
    const bf16* Kbl = Klo + (size_t)bh * Lseq * HD;
    const bf16* Vbh = Vthi + (size_t)bh * HD * Lseq;
    const bf16* Vbl = Vtlo + (size_t)bh * HD * Lseq;
    const float* hlh = hl + h * 4095;

    uint32_t sbase = smem_u32(smc);

    auto issue_tile = [&](int kt) {
        int k0 = kt << 7;
        uint32_t kst = sbase + F_K + (kt & 1) * (2 * KTILE);
        uint32_t vst = sbase + F_V + (kt & 1) * (2 * VTILE);
#pragma unroll
        for (int v = 0; v < 2; ++v) {
            int idx = v * 512 + tid;
            int row = idx >> 3, seg = idx & 7;
            cpa16(kst + row * QP * 2 + seg * 16,         Kbh + (size_t)(k0 + row) * HD + seg * 8);
            cpa16(kst + KTILE + row * QP * 2 + seg * 16, Kbl + (size_t)(k0 + row) * HD + seg * 8);
            int vrow = idx >> 4, vseg = idx & 15;
            cpa16(vst + vrow * VP * 2 + vseg * 16,         Vbh + (size_t)vrow * Lseq + k0 + vseg * 8);
            cpa16(vst + VTILE + vrow * VP * 2 + vseg * 16, Vbl + (size_t)vrow * Lseq + k0 + vseg * 8);
        }
        cpa_commit();
        if (tid < 255) win[(kt & 1) * 256 + tid] = hlh[k0 - q0 + 1920 + tid];
    };

    issue_tile(0);

#pragma unroll
    for (int v = 0; v < 2; ++v) {
        int idx = v * 512 + tid;
        int row = idx >> 3, seg = idx & 7;
        *(uint4*)(sQh + row * QP + seg * 8) = *(const uint4*)(Qbh + (size_t)(q0 + row) * HD + seg * 8);
        *(uint4*)(sQl + row * QP + seg * 8) = *(const uint4*)(Qbl + (size_t)(q0 + row) * HD + seg * 8);
    }
    if (tid < 128) { smM[tid] = -1e30f; smL[tid] = 0.f; }

    uint32_t sQh32 = smem_u32(sQh), sQl32 = smem_u32(sQl);

    uint32_t qOff[2], kOff[2], vOff[4];
#pragma unroll
    for (int im = 0; im < 2; ++im)
        qOff[im] = (uint32_t)(((wm * 32 + im * 16 + (lane & 15)) * QP + ((lane >> 4) << 3)) * 2);
    int kq = (lane & 8) ? 8 : 0;
#pragma unroll
    for (int p = 0; p < 2; ++p)
        kOff[p] = (uint32_t)(((wn * 32 + p * 16 + ((lane & 16) >> 1) + (lane & 7)) * QP + kq) * 2);
#pragma unroll
    for (int p = 0; p < 4; ++p)
        vOff[p] = (uint32_t)(((p * 16 + ((lane & 16) >> 1) + (lane & 7)) * VP + wn * 32 + kq) * 2);

    int rbase = wm * 32 + (lane >> 2);
    int cbase = wn * 32 + 2 * (lane & 3);

    float O[2][8][4];
#pragma unroll
    for (int im = 0; im < 2; ++im)
#pragma unroll
        for (int nf = 0; nf < 8; ++nf)
#pragma unroll
            for (int e = 0; e < 4; ++e) O[im][nf][e] = 0.f;

    for (int kt = 0; kt < Lseq / 128; ++kt) {
        if (kt < Lseq / 128 - 1) { issue_tile(kt + 1); cpa_wait1(); }
        else                     { cpa_wait0(); }
        __syncthreads();

        uint32_t kb = sbase + F_K + (kt & 1) * (2 * KTILE);
        uint32_t vb = sbase + F_V + (kt & 1) * (2 * VTILE);
        const float* winc = win + (kt & 1) * 256;

        float c[2][4][4];
#pragma unroll
        for (int im = 0; im < 2; ++im)
#pragma unroll
            for (int nf = 0; nf < 4; ++nf)
#pragma unroll
                for (int e = 0; e < 4; ++e) c[im][nf][e] = 0.f;
#pragma unroll
        for (int ks = 0; ks < 64; ks += 16) {
            uint32_t aH[2][4], aL[2][4], bH[2][4], bL[2][4];
#pragma unroll
            for (int im = 0; im < 2; ++im) {
                ldsm4(aH[im], sQh32 + qOff[im] + ks * 2);
                ldsm4(aL[im], sQl32 + qOff[im] + ks * 2);
            }
#pragma unroll
            for (int p = 0; p < 2; ++p) {
                ldsm4(bH[p], kb + kOff[p] + ks * 2);
                ldsm4(bL[p], kb + KTILE + kOff[p] + ks * 2);
            }
#pragma unroll
            for (int im = 0; im < 2; ++im)
#pragma unroll
                for (int nf = 0; nf < 4; ++nf)
                    mma_bf16(c[im][nf], aH[im], &bH[nf >> 1][(nf & 1) * 2]);
#pragma unroll
            for (int im = 0; im < 2; ++im)
#pragma unroll
                for (int nf = 0; nf < 4; ++nf)
                    mma_bf16(c[im][nf], aH[im], &bL[nf >> 1][(nf & 1) * 2]);
#pragma unroll
            for (int im = 0; im < 2; ++im)
#pragma unroll
                for (int nf = 0; nf < 4; ++nf)
                    mma_bf16(c[im][nf], aL[im], &bH[nf >> 1][(nf & 1) * 2]);
        }

#pragma unroll
        for (int im = 0; im < 2; ++im) {
            int row = rbase + im * 16;
            float ma = -1e30f, mb = -1e30f;
#pragma unroll
            for (int nf = 0; nf < 4; ++nf) {
                int idx = cbase + nf * 8 - row + 127;
                c[im][nf][0] += winc[idx];
                c[im][nf][1] += winc[idx + 1];
                c[im][nf][2] += winc[idx - 8];
                c[im][nf][3] += winc[idx - 7];
                ma = fmaxf(ma, fmaxf(c[im][nf][0], c[im][nf][1]));
                mb = fmaxf(mb, fmaxf(c[im][nf][2], c[im][nf][3]));
            }
            ma = fmaxf(ma, __shfl_xor_sync(0xffffffffu, ma, 1));
            ma = fmaxf(ma, __shfl_xor_sync(0xffffffffu, ma, 2));
            mb = fmaxf(mb, __shfl_xor_sync(0xffffffffu, mb, 1));
            mb = fmaxf(mb, __shfl_xor_sync(0xffffffffu, mb, 2));
            if ((lane & 3) == 0) {
                pm[row * 4 + wn] = ma;
                pm[(row + 8) * 4 + wn] = mb;
            }
        }
        __syncthreads();
        if (tid < 128) {
            float mo = smM[tid];
            float mn = fmaxf(fmaxf(pm[tid * 4], pm[tid * 4 + 1]),
                             fmaxf(pm[tid * 4 + 2], pm[tid * 4 + 3]));
            mn = fmaxf(mo, mn);
            smA[tid] = exp2f((mo - mn) * LOG2E);
            smM[tid] = mn;
        }
        __syncthreads();

#pragma unroll
        for (int im = 0; im < 2; ++im) {
            int row = rbase + im * 16;
            float mr = smM[row], mr8 = smM[row + 8];
            float sa = 0.f, sb = 0.f;
#pragma unroll
            for (int nf = 0; nf < 4; ++nf) {
                c[im][nf][0] = exp2f((c[im][nf][0] - mr) * LOG2E);
                c[im][nf][1] = exp2f((c[im][nf][1] - mr) * LOG2E);
                c[im][nf][2] = exp2f((c[im][nf][2] - mr8) * LOG2E);
                c[im][nf][3] = exp2f((c[im][nf][3] - mr8) * LOG2E);
                sa += c[im][nf][0] + c[im][nf][1];
                sb += c[im][nf][2] + c[im][nf][3];
            }
            sa += __shfl_xor_sync(0xffffffffu, sa, 1);
            sa += __shfl_xor_sync(0xffffffffu, sa, 2);
            sb += __shfl_xor_sync(0xffffffffu, sb, 1);
            sb += __shfl_xor_sync(0xffffffffu, sb, 2);
            if ((lane & 3) == 0) {
                ps[row * 4 + wn] = sa;
                ps[(row + 8) * 4 + wn] = sb;
            }
            float al = smA[row], al8 = smA[row + 8];
#pragma unroll
            for (int nf = 0; nf < 4; ++nf) {
                O[im][nf][0] *= al;      O[im][nf][1] *= al;
                O[im][nf][2] *= al8;     O[im][nf][3] *= al8;
                O[im][nf + 4][0] *= al;  O[im][nf + 4][1] *= al;
                O[im][nf + 4][2] *= al8; O[im][nf + 4][3] *= al8;
            }
        }
        __syncthreads();
        if (tid < 128)
            smL[tid] = smL[tid] * smA[tid]
                     + ps[tid * 4] + ps[tid * 4 + 1] + ps[tid * 4 + 2] + ps[tid * 4 + 3];

        // ---- pack P; term-major PV over this warp's 32-key quadrant ----
        uint32_t aPh[2][2][4], aPl[2][2][4];
#pragma unroll
        for (int kp = 0; kp < 2; ++kp)
#pragma unroll
            for (int im = 0; im < 2; ++im) {
                aPh[kp][im][0] = packsplit(c[im][2 * kp][0],     c[im][2 * kp][1],     aPl[kp][im][0]);
                aPh[kp][im][1] = packsplit(c[im][2 * kp][2],     c[im][2 * kp][3],     aPl[kp][im][1]);
                aPh[kp][im][2] = packsplit(c[im][2 * kp + 1][0], c[im][2 * kp + 1][1], aPl[kp][im][2]);
                aPh[kp][im][3] = packsplit(c[im][2 * kp + 1][2], c[im][2 * kp + 1][3], aPl[kp][im][3]);
            }
#pragma unroll
        for (int p = 0; p < 4; ++p) {
            uint32_t vH[2][4], vL[2][4];
#pragma unroll
            for (int kp = 0; kp < 2; ++kp) {
                ldsm4(vH[kp], vb + vOff[p] + kp * 32);
                ldsm4(vL[kp], vb + VTILE + vOff[p] + kp * 32);
            }
            // term PhVh: 8 independent MMAs
#pragma unroll
            for (int kp = 0; kp < 2; ++kp)
#pragma unroll
                for (int im = 0; im < 2; ++im)
#pragma unroll
                    for (int nfl = 0; nfl < 2; ++nfl)
                        mma_bf16(O[im][p * 2 + nfl], aPh[kp][im], &vH[kp][nfl * 2]);
            // term PlVh
#pragma unroll
            for (int kp = 0; kp < 2; ++kp)
#pragma unroll
                for (int im = 0; im < 2; ++im)
#pragma unroll
                    for (int nfl = 0; nfl < 2; ++nfl)
                        mma_bf16(O[im][p * 2 + nfl], aPl[kp][im], &vH[kp][nfl * 2]);
            // term PhVl
#pragma unroll
            for (int kp = 0; kp < 2; ++kp)
#pragma unroll
                for (int im = 0; im < 2; ++im)
#pragma unroll
                    for (int nfl = 0; nfl < 2; ++nfl)
                        mma_bf16(O[im][p * 2 + nfl], aPh[kp][im], &vL[kp][nfl * 2]);
        }
        __syncthreads();
    }

    int colb = 2 * (lane & 3);
    if (wn == 3) {
#pragma unroll
        for (int im = 0; im < 2; ++im) {
            int row = rbase + im * 16;
#pragma unroll
            for (int nf = 0; nf < 8; ++nf) {
                int col = nf * 8 + colb;
                *(float2*)(obuf + row * 64 + col)       = make_float2(O[im][nf][0], O[im][nf][1]);
                *(float2*)(obuf + (row + 8) * 64 + col) = make_float2(O[im][nf][2], O[im][nf][3]);
            }
        }
    }
    __syncthreads();
    if (wn == 2) {
#pragma unroll
        for (int im = 0; im < 2; ++im) {
            int row = rbase + im * 16;
#pragma unroll
            for (int nf = 0; nf < 8; ++nf) {
                int col = nf * 8 + colb;
                float2 t0 = *(float2*)(obuf + row * 64 + col);
                float2 t1 = *(float2*)(obuf + (row + 8) * 64 + col);
                *(float2*)(obuf + row * 64 + col)       = make_float2(t0.x + O[im][nf][0], t0.y + O[im][nf][1]);
                *(float2*)(obuf + (row + 8) * 64 + col) = make_float2(t1.x + O[im][nf][2], t1.y + O[im][nf][3]);
            }
        }
    }
    __syncthreads();
    if (wn == 1) {
#pragma unroll
        for (int im = 0; im < 2; ++im) {
            int row = rbase + im * 16;
#pragma unroll
            for (int nf = 0; nf < 8; ++nf) {
                int col = nf * 8 + colb;
                float2 t0 = *(float2*)(obuf + row * 64 + col);
                float2 t1 = *(float2*)(obuf + (row + 8) * 64 + col);
                *(float2*)(obuf + row * 64 + col)       = make_float2(t0.x + O[im][nf][0], t0.y + O[im][nf][1]);
                *(float2*)(obuf + (row + 8) * 64 + col) = make_float2(t1.x + O[im][nf][2], t1.y + O[im][nf][3]);
            }
        }
    }
    __syncthreads();
    if (wn == 0) {
#pragma unroll
        for (int im = 0; im < 2; ++im) {
            int row = rbase + im * 16;
            float inv = 1.f / smL[row], inv8 = 1.f / smL[row + 8];
#pragma unroll
            for (int nf = 0; nf < 8; ++nf) {
                int col = nf * 8 + colb;
                float2 t0 = *(float2*)(obuf + row * 64 + col);
                float2 t1 = *(float2*)(obuf + (row + 8) * 64 + col);
                float f0 = (O[im][nf][0] + t0.x) * inv;
                float f1 = (O[im][nf][1] + t0.y) * inv;
                float f2 = (O[im][nf][2] + t1.x) * inv8;
                float f3 = (O[im][nf][3] + t1.y) * inv8;
                size_t o0 = ((size_t)(b * Lseq + q0 + row)) * Dmod + h * HD + col;
                size_t o1 = o0 + 8 * Dmod;
                uint32_t lo0, lo1;
                uint32_t hi0 = packsplit(f0, f1, lo0);
                uint32_t hi1 = packsplit(f2, f3, lo1);
                *(uint32_t*)(Chi + o0) = hi0;
                *(uint32_t*)(Clo + o0) = lo0;
                *(uint32_t*)(Chi + o1) = hi1;
                *(uint32_t*)(Clo + o1) = lo1;
            }
        }
    }
}

// ============================================================
extern "C" void kernel_launch(void* const* d_in, const int* in_sizes, int n_in,
                              void* d_out, int out_size)
{
    const float* X  = (const float*)d_in[0];
    const float* Wq = (const float*)d_in[1];
    const float* Wk = (const float*)d_in[2];
    const float* Wv = (const float*)d_in[3];
    const float* Wo = (const float*)d_in[4];
    const float* bt = (const float*)d_in[5];
    float* out = (float*)d_out;

    void *pXhi, *pXlo, *pWhi, *pWlo, *pQhi, *pQlo, *pKhi, *pKlo,
         *pVthi, *pVtlo, *pChi, *pClo, *pF, *pHL, *pO;
    cudaGetSymbolAddress(&pXhi, g_Xhi);   cudaGetSymbolAddress(&pXlo, g_Xlo);
    cudaGetSymbolAddress(&pWhi, g_Whi);   cudaGetSymbolAddress(&pWlo, g_Wlo);
    cudaGetSymbolAddress(&pQhi, g_Qhi);   cudaGetSymbolAddress(&pQlo, g_Qlo);
    cudaGetSymbolAddress(&pKhi, g_Khi);   cudaGetSymbolAddress(&pKlo, g_Klo);
    cudaGetSymbolAddress(&pVthi, g_Vthi); cudaGetSymbolAddress(&pVtlo, g_Vtlo);
    cudaGetSymbolAddress(&pChi, g_Chi);   cudaGetSymbolAddress(&pClo, g_Clo);
    cudaGetSymbolAddress(&pF, g_F);
    cudaGetSymbolAddress(&pHL, g_HL);     cudaGetSymbolAddress(&pO, g_O);

    bf16 *Xhi = (bf16*)pXhi, *Xlo = (bf16*)pXlo;
    bf16 *Whi = (bf16*)pWhi, *Wlo = (bf16*)pWlo;
    bf16 *Qhi = (bf16*)pQhi, *Qlo = (bf16*)pQlo;
    bf16 *Khi = (bf16*)pKhi, *Klo = (bf16*)pKlo;
    bf16 *Vthi = (bf16*)pVthi, *Vtlo = (bf16*)pVtlo;
    bf16 *Chi = (bf16*)pChi, *Clo = (bf16*)pClo;
    float *Fb = (float*)pF, *HL = (float*)pHL, *Ob = (float*)pO;

    float* outp = Ob;
    float* pbp  = nullptr;
    long long osz = (long long)out_size;
    if (osz >= (long long)OUT_ELEMS + (long long)BIAS_ELEMS) {
        outp = out; pbp = out + (osz - (long long)BIAS_ELEMS);
    } else if (osz == (long long)BIAS_ELEMS) {
        pbp = out;
    } else if (osz >= (long long)OUT_ELEMS) {
        outp = out;
    }

    cudaFuncSetAttribute(flash_kernel, cudaFuncAttributeMaxDynamicSharedMemorySize, FLASH_SMEM);
    cudaFuncSetAttribute(qkv_kernel, cudaFuncAttributeMaxDynamicSharedMemorySize, GEMM_SMEM);
    cudaFuncSetAttribute(out_kernel, cudaFuncAttributeMaxDynamicSharedMemorySize, GEMM_SMEM);

    build_headlut_kernel<<<(Hh * 4095 + 255) / 256, 256>>>(bt, HL);                         // 1
    split_kernel<<<(OUT_ELEMS + 255) / 256, 256>>>(X, Xhi, Xlo, OUT_ELEMS);                 // 2
    splitW_kernel<<<dim3((Dmod * Dmod) / 256, 1, 4), 256>>>(Wq, Wk, Wv, Wo, Whi, Wlo);      // 3
    qkv_kernel<<<dim3(8, 32, 3), 128, GEMM_SMEM>>>(Xhi, Xlo, Whi, Wlo,
                                                   Qhi, Qlo, Khi, Klo, Fb);                 // 4
    v_packT_kernel<<<dim3(Lseq / 32, HD / 32, BH), dim3(32, 8)>>>(Fb, Vthi, Vtlo);          // 5
    flash_kernel<<<dim3(Lseq / 128, BH), 512, FLASH_SMEM>>>(
        Qhi, Qlo, Khi, Klo, Vthi, Vtlo, HL, Chi, Clo);                                      // 6
    if (pbp) fill_bias_kernel<<<dim3(Lseq, Hh), 512>>>(HL, pbp);                            // 7
    out_kernel<<<dim3(8, 32), 128, GEMM_SMEM>>>(Chi, Clo, Whi + 3 * (Dmod * Dmod),
                                                Wlo + 3 * (Dmod * Dmod), outp);             // 8
}

// round 11
// speedup vs baseline: 1.0866x; 1.0866x over previous
#include <cuda_runtime.h>
#include <cuda_bf16.h>
#include <math.h>
#include <stdint.h>

#define Bsz   2
#define Lseq  2048
#define Dmod  1024
#define Hh    16
#define HD    64
#define MROWS 4096
#define BH    32
#define OUT_ELEMS  (MROWS * Dmod)
#define BIAS_ELEMS (Hh * Lseq * Lseq)
#define LOG2E 1.4426950408889634f

typedef __nv_bfloat16 bf16;

// ---------------- scratch ----------------
__device__ bf16 g_Xhi[MROWS * Dmod], g_Xlo[MROWS * Dmod];
__device__ bf16 g_Whi[4 * Dmod * Dmod], g_Wlo[4 * Dmod * Dmod];
__device__ bf16 g_Qhi[BH * Lseq * HD], g_Qlo[BH * Lseq * HD];
__device__ bf16 g_Khi[BH * Lseq * HD], g_Klo[BH * Lseq * HD];
__device__ bf16 g_Vthi[BH * HD * Lseq], g_Vtlo[BH * HD * Lseq];
__device__ bf16 g_Chi[MROWS * Dmod], g_Clo[MROWS * Dmod];
__device__ float g_F[MROWS * Dmod];
__device__ float g_HL[Hh * 4095];
__device__ float g_O[OUT_ELEMS];

// ============================================================
// helpers
// ============================================================
__device__ __forceinline__ uint32_t smem_u32(const void* p) {
    uint32_t a;
    asm("{ .reg .u64 t; cvta.to.shared.u64 t, %1; cvt.u32.u64 %0, t; }" : "=r"(a) : "l"(p));
    return a;
}
__device__ __forceinline__ void ldsm4(uint32_t* r, uint32_t addr) {
    asm volatile("ldmatrix.sync.aligned.m8n8.x4.shared.b16 {%0,%1,%2,%3}, [%4];"
        : "=r"(r[0]), "=r"(r[1]), "=r"(r[2]), "=r"(r[3]) : "r"(addr));
}
__device__ __forceinline__ void mma_bf16(float* c, const uint32_t* a, const uint32_t* b) {
    asm volatile(
        "mma.sync.aligned.m16n8k16.row.col.f32.bf16.bf16.f32 "
        "{%0,%1,%2,%3}, {%4,%5,%6,%7}, {%8,%9}, {%0,%1,%2,%3};"
        : "+f"(c[0]), "+f"(c[1]), "+f"(c[2]), "+f"(c[3])
        : "r"(a[0]), "r"(a[1]), "r"(a[2]), "r"(a[3]), "r"(b[0]), "r"(b[1]));
}
__device__ __forceinline__ uint32_t packsplit(float x, float y, uint32_t& lo) {
    __nv_bfloat162 h = __floats2bfloat162_rn(x, y);
    float hx = __bfloat162float(h.x), hy = __bfloat162float(h.y);
    __nv_bfloat162 l = __floats2bfloat162_rn(x - hx, y - hy);
    lo = *(uint32_t*)&l;
    return *(uint32_t*)&h;
}
__device__ __forceinline__ void cpa16(uint32_t s, const void* g) {
    asm volatile("cp.async.cg.shared.global [%0], [%1], 16;" :: "r"(s), "l"(g) : "memory");
}
__device__ __forceinline__ void cpa_commit() { asm volatile("cp.async.commit_group;" ::: "memory"); }
__device__ __forceinline__ void cpa_wait1()  { asm volatile("cp.async.wait_group 1;" ::: "memory"); }
__device__ __forceinline__ void cpa_wait0()  { asm volatile("cp.async.wait_group 0;" ::: "memory"); }

// ============================================================
// T5 bias LUT (verified)
// ============================================================
__global__ void build_headlut_kernel(const float* __restrict__ bt, float* __restrict__ hl)
{
    int idx = blockIdx.x * blockDim.x + threadIdx.x;
    if (idx >= Hh * 4095) return;
    int h = idx / 4095;
    int t = idx - h * 4095;
    int rel = t - 2047;
    int bucket = (rel > 0) ? 16 : 0;
    int rp = rel < 0 ? -rel : rel;
    int add;
    if (rp < 8) {
        add = rp;
    } else {
        float v = (logf((float)rp * 0.125f) / 2.772588722239781f) * 8.0f;
        int lv = 8 + (int)v;
        if (rp == 16) lv = 10;
        else if (rp == 32) lv = 12;
        else if (rp == 64) lv = 14;
        add = lv > 15 ? 15 : lv;
    }
    bucket += add;
    hl[idx] = bt[bucket * Hh + h];
}

// ============================================================
// split / pack
// ============================================================
__device__ __forceinline__ void split1(float x, bf16& h, bf16& l) {
    h = __float2bfloat16(x);
    l = __float2bfloat16(x - __bfloat162float(h));
}

__global__ void split_kernel(const float* __restrict__ s, bf16* __restrict__ hi,
                             bf16* __restrict__ lo, int n)
{
    int i = blockIdx.x * 256 + threadIdx.x;
    if (i >= n) return;
    split1(s[i], hi[i], lo[i]);
}

__global__ void splitW_kernel(const float* __restrict__ W0, const float* __restrict__ W1,
                              const float* __restrict__ W2, const float* __restrict__ W3,
                              bf16* __restrict__ hi, bf16* __restrict__ lo)
{
    int z = blockIdx.z;
    const float* s = (z == 0) ? W0 : (z == 1) ? W1 : (z == 2) ? W2 : W3;
    int i = blockIdx.x * 256 + threadIdx.x;
    size_t o = (size_t)z * (Dmod * Dmod) + i;
    split1(s[i], hi[o], lo[o]);
}

__global__ void v_packT_kernel(const float* __restrict__ F, bf16* __restrict__ hi,
                               bf16* __restrict__ lo)
{
    __shared__ float t[32][33];
    int bh = blockIdx.z, b = bh >> 4, h = bh & 15;
    int l0 = blockIdx.x * 32, d0 = blockIdx.y * 32;
    int tx = threadIdx.x, ty = threadIdx.y;
#pragma unroll
    for (int r = 0; r < 4; ++r) {
        int l = l0 + ty + r * 8;
        t[ty + r * 8][tx] = F[((size_t)(b * Lseq + l)) * Dmod + h * HD + d0 + tx];
    }
    __syncthreads();
#pragma unroll
    for (int r = 0; r < 4; ++r) {
        int d = d0 + ty + r * 8;
        int l = l0 + tx;
        size_t o = ((size_t)bh * HD + d) * Lseq + l;
        split1(t[tx][ty + r * 8], hi[o], lo[o]);
    }
}

// ============================================================
// 128-thread split-bf16 HMMA GEMM (verified R9/R10)
// ============================================================
#define PITCH 40
#define TILEB (128 * PITCH * 2)
#define GEMM_SMEM (2 * 4 * TILEB)

__device__ __forceinline__ void hg_mainloop(
    const bf16* __restrict__ Abh, const bf16* __restrict__ Abl,
    const bf16* __restrict__ Bbh, const bf16* __restrict__ Bbl,
    float c[4][8][4], char* smraw)
{
    int tid = threadIdx.x, lane = tid & 31, wid = tid >> 5;
    int wm = wid >> 1, wn = wid & 1;
    uint32_t sb = smem_u32(smraw);

    int lrow = tid >> 2, lseg = tid & 3;

    uint32_t aOff[4], bOff[4];
#pragma unroll
    for (int im = 0; im < 4; ++im)
        aOff[im] = (uint32_t)(((wm * 64 + im * 16 + (lane & 15)) * PITCH + ((lane >> 4) << 3)) * 2);
    int kq = (lane & 8) ? 8 : 0;
#pragma unroll
    for (int p = 0; p < 4; ++p)
        bOff[p] = (uint32_t)(((wn * 64 + p * 16 + ((lane & 16) >> 1) + (lane & 7)) * PITCH + kq) * 2);

#pragma unroll
    for (int v = 0; v < 4; ++v) {
        int row = lrow + v * 32;
        uint32_t st = sb + (uint32_t)(row * PITCH * 2 + lseg * 16);
        size_t goff = (size_t)row * Dmod + lseg * 8;
        cpa16(st,             Abh + goff);
        cpa16(st + TILEB,     Abl + goff);
        cpa16(st + 2 * TILEB, Bbh + goff);
        cpa16(st + 3 * TILEB, Bbl + goff);
    }
    cpa_commit();

    for (int kc = 0; kc < 32; ++kc) {
        if (kc < 31) {
            int k0 = (kc + 1) << 5;
            uint32_t stg = sb + ((kc + 1) & 1) * (4 * TILEB);
#pragma unroll
            for (int v = 0; v < 4; ++v) {
                int row = lrow + v * 32;
                uint32_t st = stg + (uint32_t)(row * PITCH * 2 + lseg * 16);
                size_t goff = (size_t)row * Dmod + k0 + lseg * 8;
                cpa16(st,             Abh + goff);
                cpa16(st + TILEB,     Abl + goff);
                cpa16(st + 2 * TILEB, Bbh + goff);
                cpa16(st + 3 * TILEB, Bbl + goff);
            }
            cpa_commit();
            cpa_wait1();
        } else {
            cpa_wait0();
        }
        __syncthreads();

        uint32_t stg = sb + (kc & 1) * (4 * TILEB);
#pragma unroll
        for (int ks = 0; ks < 32; ks += 16) {
            uint32_t aH[4][4], aL[4][4];
#pragma unroll
            for (int im = 0; im < 4; ++im) {
                ldsm4(aH[im], stg + aOff[im] + ks * 2);
                ldsm4(aL[im], stg + TILEB + aOff[im] + ks * 2);
            }
#pragma unroll
            for (int ph = 0; ph < 2; ++ph) {
                uint32_t bH[2][4], bL[2][4];
#pragma unroll
                for (int pp = 0; pp < 2; ++pp) {
                    int p = ph * 2 + pp;
                    ldsm4(bH[pp], stg + 2 * TILEB + bOff[p] + ks * 2);
                    ldsm4(bL[pp], stg + 3 * TILEB + bOff[p] + ks * 2);
                }
#pragma unroll
                for (int im = 0; im < 4; ++im)
#pragma unroll
                    for (int pp = 0; pp < 2; ++pp)
#pragma unroll
                        for (int nfl = 0; nfl < 2; ++nfl)
                            mma_bf16(c[im][ph * 4 + pp * 2 + nfl], aH[im], &bH[pp][nfl * 2]);
#pragma unroll
                for (int im = 0; im < 4; ++im)
#pragma unroll
                    for (int pp = 0; pp < 2; ++pp)
#pragma unroll
                        for (int nfl = 0; nfl < 2; ++nfl)
                            mma_bf16(c[im][ph * 4 + pp * 2 + nfl], aH[im], &bL[pp][nfl * 2]);
#pragma unroll
                for (int im = 0; im < 4; ++im)
#pragma unroll
                    for (int pp = 0; pp < 2; ++pp)
#pragma unroll
                        for (int nfl = 0; nfl < 2; ++nfl)
                            mma_bf16(c[im][ph * 4 + pp * 2 + nfl], aL[im], &bH[pp][nfl * 2]);
            }
        }
        __syncthreads();
    }
}

__global__ void __launch_bounds__(128, 2) qkv_kernel(
    const bf16* __restrict__ Xhi, const bf16* __restrict__ Xlo,
    const bf16* __restrict__ Whi, const bf16* __restrict__ Wlo,
    bf16* __restrict__ Qhi, bf16* __restrict__ Qlo,
    bf16* __restrict__ Khi, bf16* __restrict__ Klo,
    float* __restrict__ F)
{
    extern __shared__ char smraw[];
    int z = blockIdx.z;
    int m0 = blockIdx.y << 7, n0 = blockIdx.x << 7;
    const size_t WSZ = (size_t)Dmod * Dmod;
    const bf16* Abh = Xhi + (size_t)m0 * Dmod;
    const bf16* Abl = Xlo + (size_t)m0 * Dmod;
    const bf16* Bbh = Whi + (size_t)z * WSZ + (size_t)n0 * Dmod;
    const bf16* Bbl = Wlo + (size_t)z * WSZ + (size_t)n0 * Dmod;

    float c[4][8][4];
#pragma unroll
    for (int im = 0; im < 4; ++im)
#pragma unroll
        for (int nf = 0; nf < 8; ++nf)
#pragma unroll
            for (int e = 0; e < 4; ++e) c[im][nf][e] = 0.f;

    hg_mainloop(Abh, Abl, Bbh, Bbl, c, smraw);

    int lane = threadIdx.x & 31, wid = threadIdx.x >> 5;
    int wm = wid >> 1, wn = wid & 1;
    bf16* Dhi = (z == 0) ? Qhi : Khi;
    bf16* Dlo = (z == 0) ? Qlo : Klo;

#pragma unroll
    for (int im = 0; im < 4; ++im) {
#pragma unroll
        for (int nf = 0; nf < 8; ++nf) {
            int row = m0 + wm * 64 + im * 16 + (lane >> 2);
            int col = n0 + wn * 64 + nf * 8 + 2 * (lane & 3);
            if (z == 2) {
                *(float2*)(F + (size_t)row * Dmod + col)       = make_float2(c[im][nf][0], c[im][nf][1]);
                *(float2*)(F + (size_t)(row + 8) * Dmod + col) = make_float2(c[im][nf][2], c[im][nf][3]);
            } else {
                int b = row >> 11, h = col >> 6, d = col & 63;
                size_t o0 = (((size_t)(b * Hh + h)) * Lseq + (row & 2047)) * HD + d;
                size_t o1 = o0 + 8 * HD;
                uint32_t lo0, lo1;
                uint32_t hi0 = packsplit(c[im][nf][0], c[im][nf][1], lo0);
                uint32_t hi1 = packsplit(c[im][nf][2], c[im][nf][3], lo1);
                *(uint32_t*)(Dhi + o0) = hi0;
                *(uint32_t*)(Dlo + o0) = lo0;
                *(uint32_t*)(Dhi + o1) = hi1;
                *(uint32_t*)(Dlo + o1) = lo1;
            }
        }
    }
}

__global__ void __launch_bounds__(128, 2) out_kernel(
    const bf16* __restrict__ Chi, const bf16* __restrict__ Clo,
    const bf16* __restrict__ Whi, const bf16* __restrict__ Wlo,
    float* __restrict__ outF)
{
    extern __shared__ char smraw[];
    int m0 = blockIdx.y << 7, n0 = blockIdx.x << 7;
    const bf16* Abh = Chi + (size_t)m0 * Dmod;
    const bf16* Abl = Clo + (size_t)m0 * Dmod;
    const bf16* Bbh = Whi + (size_t)n0 * Dmod;
    const bf16* Bbl = Wlo + (size_t)n0 * Dmod;

    float c[4][8][4];
#pragma unroll
    for (int im = 0; im < 4; ++im)
#pragma unroll
        for (int nf = 0; nf < 8; ++nf)
#pragma unroll
            for (int e = 0; e < 4; ++e) c[im][nf][e] = 0.f;

    hg_mainloop(Abh, Abl, Bbh, Bbl, c, smraw);

    int lane = threadIdx.x & 31, wid = threadIdx.x >> 5;
    int wm = wid >> 1, wn = wid & 1;
#pragma unroll
    for (int im = 0; im < 4; ++im) {
#pragma unroll
        for (int nf = 0; nf < 8; ++nf) {
            int row = m0 + wm * 64 + im * 16 + (lane >> 2);
            int col = n0 + wn * 64 + nf * 8 + 2 * (lane & 3);
            *(float2*)(outF + (size_t)row * Dmod + col)       = make_float2(c[im][nf][0], c[im][nf][1]);
            *(float2*)(outF + (size_t)(row + 8) * Dmod + col) = make_float2(c[im][nf][2], c[im][nf][3]);
        }
    }
}

// ============================================================
// Flash attention: per-warp-quadrant online softmax (register state),
// 2 syncs/tile, bias fill fused as grid.z==1 blocks.
// ============================================================
#define QP 72
#define VP 136
#define KTILE (128 * QP * 2)
#define VTILE (64 * VP * 2)
#define F_QH 0
#define F_QL (F_QH + KTILE)
#define F_K  (F_QL + KTILE)
#define F_V  (F_K + 2 * 2 * KTILE)
#define F_WIN (F_V + 2 * 2 * VTILE)
#define F_PM  (F_WIN + 2048)
#define F_PS  (F_PM + 2048)
#define FLASH_SMEM (F_PS + 2048)

__global__ void __launch_bounds__(512, 1) flash_kernel(
    const bf16* __restrict__ Qhi, const bf16* __restrict__ Qlo,
    const bf16* __restrict__ Khi, const bf16* __restrict__ Klo,
    const bf16* __restrict__ Vthi, const bf16* __restrict__ Vtlo,
    const float* __restrict__ hl, float* __restrict__ pb,
    bf16* __restrict__ Chi, bf16* __restrict__ Clo)
{
    // ---- fused bias fill blocks ----
    if (blockIdx.z == 1) {
        int bb = blockIdx.y * (int)gridDim.x + blockIdx.x;   // 0..511
        int tid = threadIdx.x;
        int j = tid * 4;
#pragma unroll 4
        for (int rr = 0; rr < 64; ++rr) {
            int row = bb * 64 + rr;                // h*2048 + i
            int hh = row >> 11, ii = row & 2047;
            const float* src = hl + hh * 4095 + (2047 - ii);
            float4* dst = (float4*)(pb + (size_t)row * Lseq);
            dst[tid] = make_float4(src[j], src[j + 1], src[j + 2], src[j + 3]);
        }
        return;
    }

    extern __shared__ char smc[];
    bf16* sQh = (bf16*)(smc + F_QH);
    bf16* sQl = (bf16*)(smc + F_QL);
    float* win = (float*)(smc + F_WIN);
    float* pm  = (float*)(smc + F_PM);
    float* ps  = (float*)(smc + F_PS);
    float* obuf = (float*)(smc + F_K);   // aliases K stage 0 (dead at epilogue)

    int tid = threadIdx.x, lane = tid & 31, wid = tid >> 5;
    int wm = wid >> 2, wn = wid & 3;
    int q0 = blockIdx.x << 7;
    int bh = blockIdx.y;
    int h = bh & 15, b = bh >> 4;
    const bf16* Qbh = Qhi + (size_t)bh * Lseq * HD;
    const bf16* Qbl = Qlo + (size_t)bh * Lseq * HD;
    const bf16* Kbh = Khi + (size_t)bh * Lseq * HD;
    const bf16* Kbl = Klo + (size_t)bh * Lseq * HD;
    const bf16* Vbh = Vthi + (size_t)bh * HD * Lseq;
    const bf16* Vbl = Vtlo + (size_t)bh * HD * Lseq;
    const float* hlh = hl + h * 4095;

    uint32_t sbase = smem_u32(smc);

    auto issue_tile = [&](int kt) {
        int k0 = kt << 7;
        uint32_t kst = sbase + F_K + (kt & 1) * (2 * KTILE);
        uint32_t vst = sbase + F_V + (kt & 1) * (2 * VTILE);
#pragma unroll
        for (int v = 0; v < 2; ++v) {
            int idx = v * 512 + tid;
            int row = idx >> 3, seg = idx & 7;
            cpa16(kst + row * QP * 2 + seg * 16,         Kbh + (size_t)(k0 + row) * HD + seg * 8);
            cpa16(kst + KTILE + row * QP * 2 + seg * 16, Kbl + (size_t)(k0 + row) * HD + seg * 8);
            int vrow = idx >> 4, vseg = idx & 15;
            cpa16(vst + vrow * VP * 2 + vseg * 16,         Vbh + (size_t)vrow * Lseq + k0 + vseg * 8);
            cpa16(vst + VTILE + vrow * VP * 2 + vseg * 16, Vbl + (size_t)vrow * Lseq + k0 + vseg * 8);
        }
        cpa_commit();
        if (tid < 255) win[(kt & 1) * 256 + tid] = hlh[k0 - q0 + 1920 + tid];
    };

    issue_tile(0);

#pragma unroll
    for (int v = 0; v < 2; ++v) {
        int idx = v * 512 + tid;
        int row = idx >> 3, seg = idx & 7;
        *(uint4*)(sQh + row * QP + seg * 8) = *(const uint4*)(Qbh + (size_t)(q0 + row) * HD + seg * 8);
        *(uint4*)(sQl + row * QP + seg * 8) = *(const uint4*)(Qbl + (size_t)(q0 + row) * HD + seg * 8);
    }

    uint32_t sQh32 = smem_u32(sQh), sQl32 = smem_u32(sQl);

    uint32_t qOff[2], kOff[2], vOff[4];
#pragma unroll
    for (int im = 0; im < 2; ++im)
        qOff[im] = (uint32_t)(((wm * 32 + im * 16 + (lane & 15)) * QP + ((lane >> 4) << 3)) * 2);
    int kq = (lane & 8) ? 8 : 0;
#pragma unroll
    for (int p = 0; p < 2; ++p)
        kOff[p] = (uint32_t)(((wn * 32 + p * 16 + ((lane & 16) >> 1) + (lane & 7)) * QP + kq) * 2);
#pragma unroll
    for (int p = 0; p < 4; ++p)
        vOff[p] = (uint32_t)(((p * 16 + ((lane & 16) >> 1) + (lane & 7)) * VP + wn * 32 + kq) * 2);

    int rbase = wm * 32 + (lane >> 2);
    int cbase = wn * 32 + 2 * (lane & 3);

    float O[2][8][4];
    float rm[2][2], rl[2][2];
#pragma unroll
    for (int im = 0; im < 2; ++im) {
        rm[im][0] = -1e30f; rm[im][1] = -1e30f;
        rl[im][0] = 0.f;    rl[im][1] = 0.f;
#pragma unroll
        for (int nf = 0; nf < 8; ++nf)
#pragma unroll
            for (int e = 0; e < 4; ++e) O[im][nf][e] = 0.f;
    }

    for (int kt = 0; kt < Lseq / 128; ++kt) {
        if (kt < Lseq / 128 - 1) { issue_tile(kt + 1); cpa_wait1(); }
        else                     { cpa_wait0(); }
        __syncthreads();

        uint32_t kb = sbase + F_K + (kt & 1) * (2 * KTILE);
        uint32_t vb = sbase + F_V + (kt & 1) * (2 * VTILE);
        const float* winc = win + (kt & 1) * 256;

        // ---- S = Q K^T (warp quadrant: 32 rows x 32 keys) ----
        float c[2][4][4];
#pragma unroll
        for (int im = 0; im < 2; ++im)
#pragma unroll
            for (int nf = 0; nf < 4; ++nf)
#pragma unroll
                for (int e = 0; e < 4; ++e) c[im][nf][e] = 0.f;
#pragma unroll
        for (int ks = 0; ks < 64; ks += 16) {
            uint32_t aH[2][4], aL[2][4], bH[2][4], bL[2][4];
#pragma unroll
            for (int im = 0; im < 2; ++im) {
                ldsm4(aH[im], sQh32 + qOff[im] + ks * 2);
                ldsm4(aL[im], sQl32 + qOff[im] + ks * 2);
            }
#pragma unroll
            for (int p = 0; p < 2; ++p) {
                ldsm4(bH[p], kb + kOff[p] + ks * 2);
                ldsm4(bL[p], kb + KTILE + kOff[p] + ks * 2);
            }
#pragma unroll
            for (int im = 0; im < 2; ++im)
#pragma unroll
                for (int nf = 0; nf < 4; ++nf)
                    mma_bf16(c[im][nf], aH[im], &bH[nf >> 1][(nf & 1) * 2]);
#pragma unroll
            for (int im = 0; im < 2; ++im)
#pragma unroll
                for (int nf = 0; nf < 4; ++nf)
                    mma_bf16(c[im][nf], aH[im], &bL[nf >> 1][(nf & 1) * 2]);
#pragma unroll
            for (int im = 0; im < 2; ++im)
#pragma unroll
                for (int nf = 0; nf < 4; ++nf)
                    mma_bf16(c[im][nf], aL[im], &bH[nf >> 1][(nf & 1) * 2]);
        }

        // ---- bias + per-warp-quadrant online softmax (no cross-warp sync) ----
#pragma unroll
        for (int im = 0; im < 2; ++im) {
            int row = rbase + im * 16;
            float ma = -1e30f, mb = -1e30f;
#pragma unroll
            for (int nf = 0; nf < 4; ++nf) {
                int idx = cbase + nf * 8 - row + 127;
                c[im][nf][0] += winc[idx];
                c[im][nf][1] += winc[idx + 1];
                c[im][nf][2] += winc[idx - 8];
                c[im][nf][3] += winc[idx - 7];
                ma = fmaxf(ma, fmaxf(c[im][nf][0], c[im][nf][1]));
                mb = fmaxf(mb, fmaxf(c[im][nf][2], c[im][nf][3]));
            }
            ma = fmaxf(ma, __shfl_xor_sync(0xffffffffu, ma, 1));
            ma = fmaxf(ma, __shfl_xor_sync(0xffffffffu, ma, 2));
            mb = fmaxf(mb, __shfl_xor_sync(0xffffffffu, mb, 1));
            mb = fmaxf(mb, __shfl_xor_sync(0xffffffffu, mb, 2));
            float mn0 = fmaxf(rm[im][0], ma);
            float mn1 = fmaxf(rm[im][1], mb);
            float a0 = exp2f((rm[im][0] - mn0) * LOG2E);
            float a1 = exp2f((rm[im][1] - mn1) * LOG2E);
            rm[im][0] = mn0; rm[im][1] = mn1;

            float sa = 0.f, sb = 0.f;
#pragma unroll
            for (int nf = 0; nf < 4; ++nf) {
                c[im][nf][0] = exp2f((c[im][nf][0] - mn0) * LOG2E);
                c[im][nf][1] = exp2f((c[im][nf][1] - mn0) * LOG2E);
                c[im][nf][2] = exp2f((c[im][nf][2] - mn1) * LOG2E);
                c[im][nf][3] = exp2f((c[im][nf][3] - mn1) * LOG2E);
                sa += c[im][nf][0] + c[im][nf][1];
                sb += c[im][nf][2] + c[im][nf][3];
            }
            sa += __shfl_xor_sync(0xffffffffu, sa, 1);
            sa += __shfl_xor_sync(0xffffffffu, sa, 2);
            sb += __shfl_xor_sync(0xffffffffu, sb, 1);
            sb += __shfl_xor_sync(0xffffffffu, sb, 2);
            rl[im][0] = rl[im][0] * a0 + sa;
            rl[im][1] = rl[im][1] * a1 + sb;

#pragma unroll
            for (int nf = 0; nf < 8; ++nf) {
                O[im][nf][0] *= a0; O[im][nf][1] *= a0;
                O[im][nf][2] *= a1; O[im][nf][3] *= a1;
            }
        }

        // ---- pack P, O += P V over this warp's 32-key quadrant ----
        uint32_t aPh[2][2][4], aPl[2][2][4];
#pragma unroll
        for (int kp = 0; kp < 2; ++kp)
#pragma unroll
            for (int im = 0; im < 2; ++im) {
                aPh[kp][im][0] = packsplit(c[im][2 * kp][0],     c[im][2 * kp][1],     aPl[kp][im][0]);
                aPh[kp][im][1] = packsplit(c[im][2 * kp][2],     c[im][2 * kp][3],     aPl[kp][im][1]);
                aPh[kp][im][2] = packsplit(c[im][2 * kp + 1][0], c[im][2 * kp + 1][1], aPl[kp][im][2]);
                aPh[kp][im][3] = packsplit(c[im][2 * kp + 1][2], c[im][2 * kp + 1][3], aPl[kp][im][3]);
            }
#pragma unroll
        for (int p = 0; p < 4; ++p) {
            uint32_t vH[2][4], vL[2][4];
#pragma unroll
            for (int kp = 0; kp < 2; ++kp) {
                ldsm4(vH[kp], vb + vOff[p] + kp * 32);
                ldsm4(vL[kp], vb + VTILE + vOff[p] + kp * 32);
            }
#pragma unroll
            for (int kp = 0; kp < 2; ++kp)
#pragma unroll
                for (int im = 0; im < 2; ++im)
#pragma unroll
                    for (int nfl = 0; nfl < 2; ++nfl)
                        mma_bf16(O[im][p * 2 + nfl], aPh[kp][im], &vH[kp][nfl * 2]);
#pragma unroll
            for (int kp = 0; kp < 2; ++kp)
#pragma unroll
                for (int im = 0; im < 2; ++im)
#pragma unroll
                    for (int nfl = 0; nfl < 2; ++nfl)
                        mma_bf16(O[im][p * 2 + nfl], aPl[kp][im], &vH[kp][nfl * 2]);
#pragma unroll
            for (int kp = 0; kp < 2; ++kp)
#pragma unroll
                for (int im = 0; im < 2; ++im)
#pragma unroll
                    for (int nfl = 0; nfl < 2; ++nfl)
                        mma_bf16(O[im][p * 2 + nfl], aPh[kp][im], &vL[kp][nfl * 2]);
        }
        __syncthreads();
    }

    // ---- merge warp quadrants: global m per row, rescale O and l ----
#pragma unroll
    for (int im = 0; im < 2; ++im)
#pragma unroll
        for (int hf = 0; hf < 2; ++hf)
            if ((lane & 3) == 0)
                pm[(rbase + im * 16 + hf * 8) * 4 + wn] = rm[im][hf];
    __syncthreads();
#pragma unroll
    for (int im = 0; im < 2; ++im) {
#pragma unroll
        for (int hf = 0; hf < 2; ++hf) {
            int row = rbase + im * 16 + hf * 8;
            float mg = fmaxf(fmaxf(pm[row * 4], pm[row * 4 + 1]),
                             fmaxf(pm[row * 4 + 2], pm[row * 4 + 3]));
            float sw = exp2f((rm[im][hf] - mg) * LOG2E);
#pragma unroll
            for (int nf = 0; nf < 8; ++nf) {
                O[im][nf][hf * 2]     *= sw;
                O[im][nf][hf * 2 + 1] *= sw;
            }
            if ((lane & 3) == 0) ps[row * 4 + wn] = rl[im][hf] * sw;
        }
    }
    __syncthreads();

    // ---- 4-way cross-warp O reduction via obuf ----
    int colb = 2 * (lane & 3);
    if (wn == 3) {
#pragma unroll
        for (int im = 0; im < 2; ++im) {
            int row = rbase + im * 16;
#pragma unroll
            for (int nf = 0; nf < 8; ++nf) {
                int col = nf * 8 + colb;
                *(float2*)(obuf + row * 64 + col)       = make_float2(O[im][nf][0], O[im][nf][1]);
                *(float2*)(obuf + (row + 8) * 64 + col) = make_float2(O[im][nf][2], O[im][nf][3]);
            }
        }
    }
    __syncthreads();
    if (wn == 2) {
#pragma unroll
        for (int im = 0; im < 2; ++im) {
            int row = rbase + im * 16;
#pragma unroll
            for (int nf = 0; nf < 8; ++nf) {
                int col = nf * 8 + colb;
                float2 t0 = *(float2*)(obuf + row * 64 + col);
                float2 t1 = *(float2*)(obuf + (row + 8) * 64 + col);
                *(float2*)(obuf + row * 64 + col)       = make_float2(t0.x + O[im][nf][0], t0.y + O[im][nf][1]);
                *(float2*)(obuf + (row + 8) * 64 + col) = make_float2(t1.x + O[im][nf][2], t1.y + O[im][nf][3]);
            }
        }
    }
    __syncthreads();
    if (wn == 1) {
#pragma unroll
        for (int im = 0; im < 2; ++im) {
            int row = rbase + im * 16;
#pragma unroll
            for (int nf = 0; nf < 8; ++nf) {
                int col = nf * 8 + colb;
                float2 t0 = *(float2*)(obuf + row * 64 + col);
                float2 t1 = *(float2*)(obuf + (row + 8) * 64 + col);
                *(float2*)(obuf + row * 64 + col)       = make_float2(t0.x + O[im][nf][0], t0.y + O[im][nf][1]);
                *(float2*)(obuf + (row + 8) * 64 + col) = make_float2(t1.x + O[im][nf][2], t1.y + O[im][nf][3]);
            }
        }
    }
    __syncthreads();
    if (wn == 0) {
#pragma unroll
        for (int im = 0; im < 2; ++im) {
            int row = rbase + im * 16;
            float l0 = ps[row * 4] + ps[row * 4 + 1] + ps[row * 4 + 2] + ps[row * 4 + 3];
            int row8 = row + 8;
            float l1 = ps[row8 * 4] + ps[row8 * 4 + 1] + ps[row8 * 4 + 2] + ps[row8 * 4 + 3];
            float inv = 1.f / l0, inv8 = 1.f / l1;
#pragma unroll
            for (int nf = 0; nf < 8; ++nf) {
                int col = nf * 8 + colb;
                float2 t0 = *(float2*)(obuf + row * 64 + col);
                float2 t1 = *(float2*)(obuf + (row + 8) * 64 + col);
                float f0 = (O[im][nf][0] + t0.x) * inv;
                float f1 = (O[im][nf][1] + t0.y) * inv;
                float f2 = (O[im][nf][2] + t1.x) * inv8;
                float f3 = (O[im][nf][3] + t1.y) * inv8;
                size_t o0 = ((size_t)(b * Lseq + q0 + row)) * Dmod + h * HD + col;
                size_t o1 = o0 + 8 * Dmod;
                uint32_t lo0, lo1;
                uint32_t hi0 = packsplit(f0, f1, lo0);
                uint32_t hi1 = packsplit(f2, f3, lo1);
                *(uint32_t*)(Chi + o0) = hi0;
                *(uint32_t*)(Clo + o0) = lo0;
                *(uint32_t*)(Chi + o1) = hi1;
                *(uint32_t*)(Clo + o1) = lo1;
            }
        }
    }
}

// ============================================================
extern "C" void kernel_launch(void* const* d_in, const int* in_sizes, int n_in,
                              void* d_out, int out_size)
{
    const float* X  = (const float*)d_in[0];
    const float* Wq = (const float*)d_in[1];
    const float* Wk = (const float*)d_in[2];
    const float* Wv = (const float*)d_in[3];
    const float* Wo = (const float*)d_in[4];
    const float* bt = (const float*)d_in[5];
    float* out = (float*)d_out;

    void *pXhi, *pXlo, *pWhi, *pWlo, *pQhi, *pQlo, *pKhi, *pKlo,
         *pVthi, *pVtlo, *pChi, *pClo, *pF, *pHL, *pO;
    cudaGetSymbolAddress(&pXhi, g_Xhi);   cudaGetSymbolAddress(&pXlo, g_Xlo);
    cudaGetSymbolAddress(&pWhi, g_Whi);   cudaGetSymbolAddress(&pWlo, g_Wlo);
    cudaGetSymbolAddress(&pQhi, g_Qhi);   cudaGetSymbolAddress(&pQlo, g_Qlo);
    cudaGetSymbolAddress(&pKhi, g_Khi);   cudaGetSymbolAddress(&pKlo, g_Klo);
    cudaGetSymbolAddress(&pVthi, g_Vthi); cudaGetSymbolAddress(&pVtlo, g_Vtlo);
    cudaGetSymbolAddress(&pChi, g_Chi);   cudaGetSymbolAddress(&pClo, g_Clo);
    cudaGetSymbolAddress(&pF, g_F);
    cudaGetSymbolAddress(&pHL, g_HL);     cudaGetSymbolAddress(&pO, g_O);

    bf16 *Xhi = (bf16*)pXhi, *Xlo = (bf16*)pXlo;
    bf16 *Whi = (bf16*)pWhi, *Wlo = (bf16*)pWlo;
    bf16 *Qhi = (bf16*)pQhi, *Qlo = (bf16*)pQlo;
    bf16 *Khi = (bf16*)pKhi, *Klo = (bf16*)pKlo;
    bf16 *Vthi = (bf16*)pVthi, *Vtlo = (bf16*)pVtlo;
    bf16 *Chi = (bf16*)pChi, *Clo = (bf16*)pClo;
    float *Fb = (float*)pF, *HL = (float*)pHL, *Ob = (float*)pO;

    float* outp = Ob;
    float* pbp  = nullptr;
    long long osz = (long long)out_size;
    if (osz >= (long long)OUT_ELEMS + (long long)BIAS_ELEMS) {
        outp = out; pbp = out + (osz - (long long)BIAS_ELEMS);
    } else if (osz == (long long)BIAS_ELEMS) {
        pbp = out;
    } else if (osz >= (long long)OUT_ELEMS) {
        outp = out;
    }

    cudaFuncSetAttribute(flash_kernel, cudaFuncAttributeMaxDynamicSharedMemorySize, FLASH_SMEM);
    cudaFuncSetAttribute(qkv_kernel, cudaFuncAttributeMaxDynamicSharedMemorySize, GEMM_SMEM);
    cudaFuncSetAttribute(out_kernel, cudaFuncAttributeMaxDynamicSharedMemorySize, GEMM_SMEM);

    build_headlut_kernel<<<(Hh * 4095 + 255) / 256, 256>>>(bt, HL);                         // 1
    split_kernel<<<(OUT_ELEMS + 255) / 256, 256>>>(X, Xhi, Xlo, OUT_ELEMS);                 // 2
    splitW_kernel<<<dim3((Dmod * Dmod) / 256, 1, 4), 256>>>(Wq, Wk, Wv, Wo, Whi, Wlo);      // 3
    qkv_kernel<<<dim3(8, 32, 3), 128, GEMM_SMEM>>>(Xhi, Xlo, Whi, Wlo,
                                                   Qhi, Qlo, Khi, Klo, Fb);                 // 4
    v_packT_kernel<<<dim3(Lseq / 32, HD / 32, BH), dim3(32, 8)>>>(Fb, Vthi, Vtlo);          // 5
    flash_kernel<<<dim3(Lseq / 128, BH, pbp ? 2 : 1), 512, FLASH_SMEM>>>(
        Qhi, Qlo, Khi, Klo, Vthi, Vtlo, HL, pbp, Chi, Clo);                                 // 6
    out_kernel<<<dim3(8, 32), 128, GEMM_SMEM>>>(Chi, Clo, Whi + 3 * (Dmod * Dmod),
                                                Wlo + 3 * (Dmod * Dmod), outp);             // 7
}

// round 12
// speedup vs baseline: 1.1296x; 1.0396x over previous
#include <cuda_runtime.h>
#include <cuda_bf16.h>
#include <math.h>
#include <stdint.h>

#define Bsz   2
#define Lseq  2048
#define Dmod  1024
#define Hh    16
#define HD    64
#define MROWS 4096
#define BH    32
#define OUT_ELEMS  (MROWS * Dmod)
#define BIAS_ELEMS (Hh * Lseq * Lseq)
#define LOG2E 1.4426950408889634f

typedef __nv_bfloat16 bf16;

// ---------------- scratch ----------------
__device__ bf16 g_Xhi[MROWS * Dmod], g_Xlo[MROWS * Dmod];
__device__ bf16 g_Whi[4 * Dmod * Dmod], g_Wlo[4 * Dmod * Dmod];
__device__ bf16 g_Qhi[BH * Lseq * HD], g_Qlo[BH * Lseq * HD];
__device__ bf16 g_Khi[BH * Lseq * HD], g_Klo[BH * Lseq * HD];
__device__ bf16 g_Vthi[BH * HD * Lseq], g_Vtlo[BH * HD * Lseq];
__device__ bf16 g_Chi[MROWS * Dmod], g_Clo[MROWS * Dmod];
__device__ float g_F[MROWS * Dmod];
__device__ float g_HL[Hh * 4095];
__device__ float g_O[OUT_ELEMS];

// ============================================================
// helpers
// ============================================================
__device__ __forceinline__ uint32_t smem_u32(const void* p) {
    uint32_t a;
    asm("{ .reg .u64 t; cvta.to.shared.u64 t, %1; cvt.u32.u64 %0, t; }" : "=r"(a) : "l"(p));
    return a;
}
__device__ __forceinline__ void ldsm4(uint32_t* r, uint32_t addr) {
    asm volatile("ldmatrix.sync.aligned.m8n8.x4.shared.b16 {%0,%1,%2,%3}, [%4];"
        : "=r"(r[0]), "=r"(r[1]), "=r"(r[2]), "=r"(r[3]) : "r"(addr));
}
__device__ __forceinline__ void mma_bf16(float* c, const uint32_t* a, const uint32_t* b) {
    asm volatile(
        "mma.sync.aligned.m16n8k16.row.col.f32.bf16.bf16.f32 "
        "{%0,%1,%2,%3}, {%4,%5,%6,%7}, {%8,%9}, {%0,%1,%2,%3};"
        : "+f"(c[0]), "+f"(c[1]), "+f"(c[2]), "+f"(c[3])
        : "r"(a[0]), "r"(a[1]), "r"(a[2]), "r"(a[3]), "r"(b[0]), "r"(b[1]));
}
__device__ __forceinline__ uint32_t packsplit(float x, float y, uint32_t& lo) {
    __nv_bfloat162 h = __floats2bfloat162_rn(x, y);
    float hx = __bfloat162float(h.x), hy = __bfloat162float(h.y);
    __nv_bfloat162 l = __floats2bfloat162_rn(x - hx, y - hy);
    lo = *(uint32_t*)&l;
    return *(uint32_t*)&h;
}
__device__ __forceinline__ void cpa16(uint32_t s, const void* g) {
    asm volatile("cp.async.cg.shared.global [%0], [%1], 16;" :: "r"(s), "l"(g) : "memory");
}
__device__ __forceinline__ void cpa_commit() { asm volatile("cp.async.commit_group;" ::: "memory"); }
__device__ __forceinline__ void cpa_wait0()  { asm volatile("cp.async.wait_group 0;" ::: "memory"); }

// ============================================================
// T5 bias LUT (verified)
// ============================================================
__global__ void build_headlut_kernel(const float* __restrict__ bt, float* __restrict__ hl)
{
    int idx = blockIdx.x * blockDim.x + threadIdx.x;
    if (idx >= Hh * 4095) return;
    int h = idx / 4095;
    int t = idx - h * 4095;
    int rel = t - 2047;
    int bucket = (rel > 0) ? 16 : 0;
    int rp = rel < 0 ? -rel : rel;
    int add;
    if (rp < 8) {
        add = rp;
    } else {
        float v = (logf((float)rp * 0.125f) / 2.772588722239781f) * 8.0f;
        int lv = 8 + (int)v;
        if (rp == 16) lv = 10;
        else if (rp == 32) lv = 12;
        else if (rp == 64) lv = 14;
        add = lv > 15 ? 15 : lv;
    }
    bucket += add;
    hl[idx] = bt[bucket * Hh + h];
}

// ============================================================
// split / pack
// ============================================================
__device__ __forceinline__ void split1(float x, bf16& h, bf16& l) {
    h = __float2bfloat16(x);
    l = __float2bfloat16(x - __bfloat162float(h));
}

__global__ void split_kernel(const float* __restrict__ s, bf16* __restrict__ hi,
                             bf16* __restrict__ lo, int n)
{
    int i = blockIdx.x * 256 + threadIdx.x;
    if (i >= n) return;
    split1(s[i], hi[i], lo[i]);
}

__global__ void splitW_kernel(const float* __restrict__ W0, const float* __restrict__ W1,
                              const float* __restrict__ W2, const float* __restrict__ W3,
                              bf16* __restrict__ hi, bf16* __restrict__ lo)
{
    int z = blockIdx.z;
    const float* s = (z == 0) ? W0 : (z == 1) ? W1 : (z == 2) ? W2 : W3;
    int i = blockIdx.x * 256 + threadIdx.x;
    size_t o = (size_t)z * (Dmod * Dmod) + i;
    split1(s[i], hi[o], lo[o]);
}

__global__ void v_packT_kernel(const float* __restrict__ F, bf16* __restrict__ hi,
                               bf16* __restrict__ lo)
{
    __shared__ float t[32][33];
    int bh = blockIdx.z, b = bh >> 4, h = bh & 15;
    int l0 = blockIdx.x * 32, d0 = blockIdx.y * 32;
    int tx = threadIdx.x, ty = threadIdx.y;
#pragma unroll
    for (int r = 0; r < 4; ++r) {
        int l = l0 + ty + r * 8;
        t[ty + r * 8][tx] = F[((size_t)(b * Lseq + l)) * Dmod + h * HD + d0 + tx];
    }
    __syncthreads();
#pragma unroll
    for (int r = 0; r < 4; ++r) {
        int d = d0 + ty + r * 8;
        int l = l0 + tx;
        size_t o = ((size_t)bh * HD + d) * Lseq + l;
        split1(t[tx][ty + r * 8], hi[o], lo[o]);
    }
}

// ============================================================
// 128-thread split-bf16 HMMA GEMM, cp.async double-buffered,
// ONE barrier per k-chunk: wait0 -> sync -> issue(next) -> MMA(cur)
// ============================================================
#define PITCH 40
#define TILEB (128 * PITCH * 2)
#define GEMM_SMEM (2 * 4 * TILEB)

__device__ __forceinline__ void hg_mainloop(
    const bf16* __restrict__ Abh, const bf16* __restrict__ Abl,
    const bf16* __restrict__ Bbh, const bf16* __restrict__ Bbl,
    float c[4][8][4], char* smraw)
{
    int tid = threadIdx.x, lane = tid & 31, wid = tid >> 5;
    int wm = wid >> 1, wn = wid & 1;
    uint32_t sb = smem_u32(smraw);

    int lrow = tid >> 2, lseg = tid & 3;

    uint32_t aOff[4], bOff[4];
#pragma unroll
    for (int im = 0; im < 4; ++im)
        aOff[im] = (uint32_t)(((wm * 64 + im * 16 + (lane & 15)) * PITCH + ((lane >> 4) << 3)) * 2);
    int kq = (lane & 8) ? 8 : 0;
#pragma unroll
    for (int p = 0; p < 4; ++p)
        bOff[p] = (uint32_t)(((wn * 64 + p * 16 + ((lane & 16) >> 1) + (lane & 7)) * PITCH + kq) * 2);

    // prologue: chunk 0 -> stage 0
#pragma unroll
    for (int v = 0; v < 4; ++v) {
        int row = lrow + v * 32;
        uint32_t st = sb + (uint32_t)(row * PITCH * 2 + lseg * 16);
        size_t goff = (size_t)row * Dmod + lseg * 8;
        cpa16(st,             Abh + goff);
        cpa16(st + TILEB,     Abl + goff);
        cpa16(st + 2 * TILEB, Bbh + goff);
        cpa16(st + 3 * TILEB, Bbl + goff);
    }
    cpa_commit();

    for (int kc = 0; kc < 32; ++kc) {
        cpa_wait0();          // group kc complete (issued prev iter / prologue)
        __syncthreads();      // publish stage kc; all warps done with MMA(kc-1)
        if (kc < 31) {
            int k0 = (kc + 1) << 5;
            uint32_t stg = sb + ((kc + 1) & 1) * (4 * TILEB);
#pragma unroll
            for (int v = 0; v < 4; ++v) {
                int row = lrow + v * 32;
                uint32_t st = stg + (uint32_t)(row * PITCH * 2 + lseg * 16);
                size_t goff = (size_t)row * Dmod + k0 + lseg * 8;
                cpa16(st,             Abh + goff);
                cpa16(st + TILEB,     Abl + goff);
                cpa16(st + 2 * TILEB, Bbh + goff);
                cpa16(st + 3 * TILEB, Bbl + goff);
            }
            cpa_commit();
        }

        uint32_t stg = sb + (kc & 1) * (4 * TILEB);
#pragma unroll
        for (int ks = 0; ks < 32; ks += 16) {
            uint32_t aH[4][4], aL[4][4];
#pragma unroll
            for (int im = 0; im < 4; ++im) {
                ldsm4(aH[im], stg + aOff[im] + ks * 2);
                ldsm4(aL[im], stg + TILEB + aOff[im] + ks * 2);
            }
#pragma unroll
            for (int ph = 0; ph < 2; ++ph) {
                uint32_t bH[2][4], bL[2][4];
#pragma unroll
                for (int pp = 0; pp < 2; ++pp) {
                    int p = ph * 2 + pp;
                    ldsm4(bH[pp], stg + 2 * TILEB + bOff[p] + ks * 2);
                    ldsm4(bL[pp], stg + 3 * TILEB + bOff[p] + ks * 2);
                }
#pragma unroll
                for (int im = 0; im < 4; ++im)
#pragma unroll
                    for (int pp = 0; pp < 2; ++pp)
#pragma unroll
                        for (int nfl = 0; nfl < 2; ++nfl)
                            mma_bf16(c[im][ph * 4 + pp * 2 + nfl], aH[im], &bH[pp][nfl * 2]);
#pragma unroll
                for (int im = 0; im < 4; ++im)
#pragma unroll
                    for (int pp = 0; pp < 2; ++pp)
#pragma unroll
                        for (int nfl = 0; nfl < 2; ++nfl)
                            mma_bf16(c[im][ph * 4 + pp * 2 + nfl], aH[im], &bL[pp][nfl * 2]);
#pragma unroll
                for (int im = 0; im < 4; ++im)
#pragma unroll
                    for (int pp = 0; pp < 2; ++pp)
#pragma unroll
                        for (int nfl = 0; nfl < 2; ++nfl)
                            mma_bf16(c[im][ph * 4 + pp * 2 + nfl], aL[im], &bH[pp][nfl * 2]);
            }
        }
    }
}

__global__ void __launch_bounds__(128, 2) qkv_kernel(
    const bf16* __restrict__ Xhi, const bf16* __restrict__ Xlo,
    const bf16* __restrict__ Whi, const bf16* __restrict__ Wlo,
    bf16* __restrict__ Qhi, bf16* __restrict__ Qlo,
    bf16* __restrict__ Khi, bf16* __restrict__ Klo,
    float* __restrict__ F)
{
    extern __shared__ char smraw[];
    int z = blockIdx.z;
    int m0 = blockIdx.y << 7, n0 = blockIdx.x << 7;
    const size_t WSZ = (size_t)Dmod * Dmod;
    const bf16* Abh = Xhi + (size_t)m0 * Dmod;
    const bf16* Abl = Xlo + (size_t)m0 * Dmod;
    const bf16* Bbh = Whi + (size_t)z * WSZ + (size_t)n0 * Dmod;
    const bf16* Bbl = Wlo + (size_t)z * WSZ + (size_t)n0 * Dmod;

    float c[4][8][4];
#pragma unroll
    for (int im = 0; im < 4; ++im)
#pragma unroll
        for (int nf = 0; nf < 8; ++nf)
#pragma unroll
            for (int e = 0; e < 4; ++e) c[im][nf][e] = 0.f;

    hg_mainloop(Abh, Abl, Bbh, Bbl, c, smraw);

    int lane = threadIdx.x & 31, wid = threadIdx.x >> 5;
    int wm = wid >> 1, wn = wid & 1;
    bf16* Dhi = (z == 0) ? Qhi : Khi;
    bf16* Dlo = (z == 0) ? Qlo : Klo;

#pragma unroll
    for (int im = 0; im < 4; ++im) {
#pragma unroll
        for (int nf = 0; nf < 8; ++nf) {
            int row = m0 + wm * 64 + im * 16 + (lane >> 2);
            int col = n0 + wn * 64 + nf * 8 + 2 * (lane & 3);
            if (z == 2) {
                *(float2*)(F + (size_t)row * Dmod + col)       = make_float2(c[im][nf][0], c[im][nf][1]);
                *(float2*)(F + (size_t)(row + 8) * Dmod + col) = make_float2(c[im][nf][2], c[im][nf][3]);
            } else {
                int b = row >> 11, h = col >> 6, d = col & 63;
                size_t o0 = (((size_t)(b * Hh + h)) * Lseq + (row & 2047)) * HD + d;
                size_t o1 = o0 + 8 * HD;
                uint32_t lo0, lo1;
                uint32_t hi0 = packsplit(c[im][nf][0], c[im][nf][1], lo0);
                uint32_t hi1 = packsplit(c[im][nf][2], c[im][nf][3], lo1);
                *(uint32_t*)(Dhi + o0) = hi0;
                *(uint32_t*)(Dlo + o0) = lo0;
                *(uint32_t*)(Dhi + o1) = hi1;
                *(uint32_t*)(Dlo + o1) = lo1;
            }
        }
    }
}

__global__ void __launch_bounds__(128, 2) out_kernel(
    const bf16* __restrict__ Chi, const bf16* __restrict__ Clo,
    const bf16* __restrict__ Whi, const bf16* __restrict__ Wlo,
    float* __restrict__ outF)
{
    extern __shared__ char smraw[];
    int m0 = blockIdx.y << 7, n0 = blockIdx.x << 7;
    const bf16* Abh = Chi + (size_t)m0 * Dmod;
    const bf16* Abl = Clo + (size_t)m0 * Dmod;
    const bf16* Bbh = Whi + (size_t)n0 * Dmod;
    const bf16* Bbl = Wlo + (size_t)n0 * Dmod;

    float c[4][8][4];
#pragma unroll
    for (int im = 0; im < 4; ++im)
#pragma unroll
        for (int nf = 0; nf < 8; ++nf)
#pragma unroll
            for (int e = 0; e < 4; ++e) c[im][nf][e] = 0.f;

    hg_mainloop(Abh, Abl, Bbh, Bbl, c, smraw);

    int lane = threadIdx.x & 31, wid = threadIdx.x >> 5;
    int wm = wid >> 1, wn = wid & 1;
#pragma unroll
    for (int im = 0; im < 4; ++im) {
#pragma unroll
        for (int nf = 0; nf < 8; ++nf) {
            int row = m0 + wm * 64 + im * 16 + (lane >> 2);
            int col = n0 + wn * 64 + nf * 8 + 2 * (lane & 3);
            *(float2*)(outF + (size_t)row * Dmod + col)       = make_float2(c[im][nf][0], c[im][nf][1]);
            *(float2*)(outF + (size_t)(row + 8) * Dmod + col) = make_float2(c[im][nf][2], c[im][nf][3]);
        }
    }
}

// ============================================================
// Flash attention: per-warp-quadrant softmax, ONE barrier per tile,
// bias fill fused as grid.z==1 blocks.
// ============================================================
#define QP 72
#define VP 136
#define KTILE (128 * QP * 2)
#define VTILE (64 * VP * 2)
#define F_QH 0
#define F_QL (F_QH + KTILE)
#define F_K  (F_QL + KTILE)
#define F_V  (F_K + 2 * 2 * KTILE)
#define F_WIN (F_V + 2 * 2 * VTILE)
#define F_PM  (F_WIN + 2048)
#define F_PS  (F_PM + 2048)
#define FLASH_SMEM (F_PS + 2048)

__global__ void __launch_bounds__(512, 1) flash_kernel(
    const bf16* __restrict__ Qhi, const bf16* __restrict__ Qlo,
    const bf16* __restrict__ Khi, const bf16* __restrict__ Klo,
    const bf16* __restrict__ Vthi, const bf16* __restrict__ Vtlo,
    const float* __restrict__ hl, float* __restrict__ pb,
    bf16* __restrict__ Chi, bf16* __restrict__ Clo)
{
    // ---- fused bias fill blocks ----
    if (blockIdx.z == 1) {
        int bb = blockIdx.y * (int)gridDim.x + blockIdx.x;
        int tid = threadIdx.x;
        int j = tid * 4;
#pragma unroll 4
        for (int rr = 0; rr < 64; ++rr) {
            int row = bb * 64 + rr;
            int hh = row >> 11, ii = row & 2047;
            const float* src = hl + hh * 4095 + (2047 - ii);
            float4* dst = (float4*)(pb + (size_t)row * Lseq);
            dst[tid] = make_float4(src[j], src[j + 1], src[j + 2], src[j + 3]);
        }
        return;
    }

    extern __shared__ char smc[];
    bf16* sQh = (bf16*)(smc + F_QH);
    bf16* sQl = (bf16*)(smc + F_QL);
    float* win = (float*)(smc + F_WIN);
    float* pm  = (float*)(smc + F_PM);
    float* ps  = (float*)(smc + F_PS);
    float* obuf = (float*)(smc + F_K);   // aliases K stage 0 (dead at epilogue: last tile uses stage 1)

    int tid = threadIdx.x, lane = tid & 31, wid = tid >> 5;
    int wm = wid >> 2, wn = wid & 3;
    int q0 = blockIdx.x << 7;
    int bh = blockIdx.y;
    int h = bh & 15, b = bh >> 4;
    const bf16* Qbh = Qhi + (size_t)bh * Lseq * HD;
    const bf16* Qbl = Qlo + (size_t)bh * Lseq * HD;
    const bf16* Kbh = Khi + (size_t)bh * Lseq * HD;
    const bf16* Kbl = Klo + (size_t)bh * Lseq * HD;
    const bf16* Vbh = Vthi + (size_t)bh * HD * Lseq;
    const bf16* Vbl = Vtlo + (size_t)bh * HD * Lseq;
    const float* hlh = hl + h * 4095;

    uint32_t sbase = smem_u32(smc);

    auto issue_tile = [&](int kt) {
        int k0 = kt << 7;
        uint32_t kst = sbase + F_K + (kt & 1) * (2 * KTILE);
        uint32_t vst = sbase + F_V + (kt & 1) * (2 * VTILE);
#pragma unroll
        for (int v = 0; v < 2; ++v) {
            int idx = v * 512 + tid;
            int row = idx >> 3, seg = idx & 7;
            cpa16(kst + row * QP * 2 + seg * 16,         Kbh + (size_t)(k0 + row) * HD + seg * 8);
            cpa16(kst + KTILE + row * QP * 2 + seg * 16, Kbl + (size_t)(k0 + row) * HD + seg * 8);
            int vrow = idx >> 4, vseg = idx & 15;
            cpa16(vst + vrow * VP * 2 + vseg * 16,         Vbh + (size_t)vrow * Lseq + k0 + vseg * 8);
            cpa16(vst + VTILE + vrow * VP * 2 + vseg * 16, Vbl + (size_t)vrow * Lseq + k0 + vseg * 8);
        }
        cpa_commit();
        if (tid < 255) win[(kt & 1) * 256 + tid] = hlh[k0 - q0 + 1920 + tid];
    };

    issue_tile(0);

#pragma unroll
    for (int v = 0; v < 2; ++v) {
        int idx = v * 512 + tid;
        int row = idx >> 3, seg = idx & 7;
        *(uint4*)(sQh + row * QP + seg * 8) = *(const uint4*)(Qbh + (size_t)(q0 + row) * HD + seg * 8);
        *(uint4*)(sQl + row * QP + seg * 8) = *(const uint4*)(Qbl + (size_t)(q0 + row) * HD + seg * 8);
    }

    uint32_t sQh32 = smem_u32(sQh), sQl32 = smem_u32(sQl);

    uint32_t qOff[2], kOff[2], vOff[4];
#pragma unroll
    for (int im = 0; im < 2; ++im)
        qOff[im] = (uint32_t)(((wm * 32 + im * 16 + (lane & 15)) * QP + ((lane >> 4) << 3)) * 2);
    int kq = (lane & 8) ? 8 : 0;
#pragma unroll
    for (int p = 0; p < 2; ++p)
        kOff[p] = (uint32_t)(((wn * 32 + p * 16 + ((lane & 16) >> 1) + (lane & 7)) * QP + kq) * 2);
#pragma unroll
    for (int p = 0; p < 4; ++p)
        vOff[p] = (uint32_t)(((p * 16 + ((lane & 16) >> 1) + (lane & 7)) * VP + wn * 32 + kq) * 2);

    int rbase = wm * 32 + (lane >> 2);
    int cbase = wn * 32 + 2 * (lane & 3);

    float O[2][8][4];
    float rm[2][2], rl[2][2];
#pragma unroll
    for (int im = 0; im < 2; ++im) {
        rm[im][0] = -1e30f; rm[im][1] = -1e30f;
        rl[im][0] = 0.f;    rl[im][1] = 0.f;
#pragma unroll
        for (int nf = 0; nf < 8; ++nf)
#pragma unroll
            for (int e = 0; e < 4; ++e) O[im][nf][e] = 0.f;
    }

    for (int kt = 0; kt < Lseq / 128; ++kt) {
        cpa_wait0();        // tile kt data locally complete
        __syncthreads();    // publish + all warps done with tile kt-1
        if (kt < Lseq / 128 - 1) issue_tile(kt + 1);

        uint32_t kb = sbase + F_K + (kt & 1) * (2 * KTILE);
        uint32_t vb = sbase + F_V + (kt & 1) * (2 * VTILE);
        const float* winc = win + (kt & 1) * 256;

        // ---- S = Q K^T (warp quadrant) ----
        float c[2][4][4];
#pragma unroll
        for (int im = 0; im < 2; ++im)
#pragma unroll
            for (int nf = 0; nf < 4; ++nf)
#pragma unroll
                for (int e = 0; e < 4; ++e) c[im][nf][e] = 0.f;
#pragma unroll
        for (int ks = 0; ks < 64; ks += 16) {
            uint32_t aH[2][4], aL[2][4], bH[2][4], bL[2][4];
#pragma unroll
            for (int im = 0; im < 2; ++im) {
                ldsm4(aH[im], sQh32 + qOff[im] + ks * 2);
                ldsm4(aL[im], sQl32 + qOff[im] + ks * 2);
            }
#pragma unroll
            for (int p = 0; p < 2; ++p) {
                ldsm4(bH[p], kb + kOff[p] + ks * 2);
                ldsm4(bL[p], kb + KTILE + kOff[p] + ks * 2);
            }
#pragma unroll
            for (int im = 0; im < 2; ++im)
#pragma unroll
                for (int nf = 0; nf < 4; ++nf)
                    mma_bf16(c[im][nf], aH[im], &bH[nf >> 1][(nf & 1) * 2]);
#pragma unroll
            for (int im = 0; im < 2; ++im)
#pragma unroll
                for (int nf = 0; nf < 4; ++nf)
                    mma_bf16(c[im][nf], aH[im], &bL[nf >> 1][(nf & 1) * 2]);
#pragma unroll
            for (int im = 0; im < 2; ++im)
#pragma unroll
                for (int nf = 0; nf < 4; ++nf)
                    mma_bf16(c[im][nf], aL[im], &bH[nf >> 1][(nf & 1) * 2]);
        }

        // ---- bias + per-warp-quadrant online softmax ----
#pragma unroll
        for (int im = 0; im < 2; ++im) {
            int row = rbase + im * 16;
            float ma = -1e30f, mb = -1e30f;
#pragma unroll
            for (int nf = 0; nf < 4; ++nf) {
                int idx = cbase + nf * 8 - row + 127;
                c[im][nf][0] += winc[idx];
                c[im][nf][1] += winc[idx + 1];
                c[im][nf][2] += winc[idx - 8];
                c[im][nf][3] += winc[idx - 7];
                ma = fmaxf(ma, fmaxf(c[im][nf][0], c[im][nf][1]));
                mb = fmaxf(mb, fmaxf(c[im][nf][2], c[im][nf][3]));
            }
            ma = fmaxf(ma, __shfl_xor_sync(0xffffffffu, ma, 1));
            ma = fmaxf(ma, __shfl_xor_sync(0xffffffffu, ma, 2));
            mb = fmaxf(mb, __shfl_xor_sync(0xffffffffu, mb, 1));
            mb = fmaxf(mb, __shfl_xor_sync(0xffffffffu, mb, 2));
            float mn0 = fmaxf(rm[im][0], ma);
            float mn1 = fmaxf(rm[im][1], mb);
            float a0 = exp2f((rm[im][0] - mn0) * LOG2E);
            float a1 = exp2f((rm[im][1] - mn1) * LOG2E);
            rm[im][0] = mn0; rm[im][1] = mn1;

            float sa = 0.f, sb = 0.f;
#pragma unroll
            for (int nf = 0; nf < 4; ++nf) {
                c[im][nf][0] = exp2f((c[im][nf][0] - mn0) * LOG2E);
                c[im][nf][1] = exp2f((c[im][nf][1] - mn0) * LOG2E);
                c[im][nf][2] = exp2f((c[im][nf][2] - mn1) * LOG2E);
                c[im][nf][3] = exp2f((c[im][nf][3] - mn1) * LOG2E);
                sa += c[im][nf][0] + c[im][nf][1];
                sb += c[im][nf][2] + c[im][nf][3];
            }
            sa += __shfl_xor_sync(0xffffffffu, sa, 1);
            sa += __shfl_xor_sync(0xffffffffu, sa, 2);
            sb += __shfl_xor_sync(0xffffffffu, sb, 1);
            sb += __shfl_xor_sync(0xffffffffu, sb, 2);
            rl[im][0] = rl[im][0] * a0 + sa;
            rl[im][1] = rl[im][1] * a1 + sb;

#pragma unroll
            for (int nf = 0; nf < 8; ++nf) {
                O[im][nf][0] *= a0; O[im][nf][1] *= a0;
                O[im][nf][2] *= a1; O[im][nf][3] *= a1;
            }
        }

        // ---- pack P, O += P V over this warp's 32-key quadrant ----
        uint32_t aPh[2][2][4], aPl[2][2][4];
#pragma unroll
        for (int kp = 0; kp < 2; ++kp)
#pragma unroll
            for (int im = 0; im < 2; ++im) {
                aPh[kp][im][0] = packsplit(c[im][2 * kp][0],     c[im][2 * kp][1],     aPl[kp][im][0]);
                aPh[kp][im][1] = packsplit(c[im][2 * kp][2],     c[im][2 * kp][3],     aPl[kp][im][1]);
                aPh[kp][im][2] = packsplit(c[im][2 * kp + 1][0], c[im][2 * kp + 1][1], aPl[kp][im][2]);
                aPh[kp][im][3] = packsplit(c[im][2 * kp + 1][2], c[im][2 * kp + 1][3], aPl[kp][im][3]);
            }
#pragma unroll
        for (int p = 0; p < 4; ++p) {
            uint32_t vH[2][4], vL[2][4];
#pragma unroll
            for (int kp = 0; kp < 2; ++kp) {
                ldsm4(vH[kp], vb + vOff[p] + kp * 32);
                ldsm4(vL[kp], vb + VTILE + vOff[p] + kp * 32);
            }
#pragma unroll
            for (int kp = 0; kp < 2; ++kp)
#pragma unroll
                for (int im = 0; im < 2; ++im)
#pragma unroll
                    for (int nfl = 0; nfl < 2; ++nfl)
                        mma_bf16(O[im][p * 2 + nfl], aPh[kp][im], &vH[kp][nfl * 2]);
#pragma unroll
            for (int kp = 0; kp < 2; ++kp)
#pragma unroll
                for (int im = 0; im < 2; ++im)
#pragma unroll
                    for (int nfl = 0; nfl < 2; ++nfl)
                        mma_bf16(O[im][p * 2 + nfl], aPl[kp][im], &vH[kp][nfl * 2]);
#pragma unroll
            for (int kp = 0; kp < 2; ++kp)
#pragma unroll
                for (int im = 0; im < 2; ++im)
#pragma unroll
                    for (int nfl = 0; nfl < 2; ++nfl)
                        mma_bf16(O[im][p * 2 + nfl], aPh[kp][im], &vL[kp][nfl * 2]);
        }
    }

    // ---- merge warp quadrants ----
#pragma unroll
    for (int im = 0; im < 2; ++im)
#pragma unroll
        for (int hf = 0; hf < 2; ++hf)
            if ((lane & 3) == 0)
                pm[(rbase + im * 16 + hf * 8) * 4 + wn] = rm[im][hf];
    __syncthreads();
#pragma unroll
    for (int im = 0; im < 2; ++im) {
#pragma unroll
        for (int hf = 0; hf < 2; ++hf) {
            int row = rbase + im * 16 + hf * 8;
            float mg = fmaxf(fmaxf(pm[row * 4], pm[row * 4 + 1]),
                             fmaxf(pm[row * 4 + 2], pm[row * 4 + 3]));
            float sw = exp2f((rm[im][hf] - mg) * LOG2E);
#pragma unroll
            for (int nf = 0; nf < 8; ++nf) {
                O[im][nf][hf * 2]     *= sw;
                O[im][nf][hf * 2 + 1] *= sw;
            }
            if ((lane & 3) == 0) ps[row * 4 + wn] = rl[im][hf] * sw;
        }
    }
    __syncthreads();

    // ---- 4-way cross-warp O reduction via obuf ----
    int colb = 2 * (lane & 3);
    if (wn == 3) {
#pragma unroll
        for (int im = 0; im < 2; ++im) {
            int row = rbase + im * 16;
#pragma unroll
            for (int nf = 0; nf < 8; ++nf) {
                int col = nf * 8 + colb;
                *(float2*)(obuf + row * 64 + col)       = make_float2(O[im][nf][0], O[im][nf][1]);
                *(float2*)(obuf + (row + 8) * 64 + col) = make_float2(O[im][nf][2], O[im][nf][3]);
            }
        }
    }
    __syncthreads();
    if (wn == 2) {
#pragma unroll
        for (int im = 0; im < 2; ++im) {
            int row = rbase + im * 16;
#pragma unroll
            for (int nf = 0; nf < 8; ++nf) {
                int col = nf * 8 + colb;
                float2 t0 = *(float2*)(obuf + row * 64 + col);
                float2 t1 = *(float2*)(obuf + (row + 8) * 64 + col);
                *(float2*)(obuf + row * 64 + col)       = make_float2(t0.x + O[im][nf][0], t0.y + O[im][nf][1]);
                *(float2*)(obuf + (row + 8) * 64 + col) = make_float2(t1.x + O[im][nf][2], t1.y + O[im][nf][3]);
            }
        }
    }
    __syncthreads();
    if (wn == 1) {
#pragma unroll
        for (int im = 0; im < 2; ++im) {
            int row = rbase + im * 16;
#pragma unroll
            for (int nf = 0; nf < 8; ++nf) {
                int col = nf * 8 + colb;
                float2 t0 = *(float2*)(obuf + row * 64 + col);
                float2 t1 = *(float2*)(obuf + (row + 8) * 64 + col);
                *(float2*)(obuf + row * 64 + col)       = make_float2(t0.x + O[im][nf][0], t0.y + O[im][nf][1]);
                *(float2*)(obuf + (row + 8) * 64 + col) = make_float2(t1.x + O[im][nf][2], t1.y + O[im][nf][3]);
            }
        }
    }
    __syncthreads();
    if (wn == 0) {
#pragma unroll
        for (int im = 0; im < 2; ++im) {
            int row = rbase + im * 16;
            float l0 = ps[row * 4] + ps[row * 4 + 1] + ps[row * 4 + 2] + ps[row * 4 + 3];
            int row8 = row + 8;
            float l1 = ps[row8 * 4] + ps[row8 * 4 + 1] + ps[row8 * 4 + 2] + ps[row8 * 4 + 3];
            float inv = 1.f / l0, inv8 = 1.f / l1;
#pragma unroll
            for (int nf = 0; nf < 8; ++nf) {
                int col = nf * 8 + colb;
                float2 t0 = *(float2*)(obuf + row * 64 + col);
                float2 t1 = *(float2*)(obuf + (row + 8) * 64 + col);
                float f0 = (O[im][nf][0] + t0.x) * inv;
                float f1 = (O[im][nf][1] + t0.y) * inv;
                float f2 = (O[im][nf][2] + t1.x) * inv8;
                float f3 = (O[im][nf][3] + t1.y) * inv8;
                size_t o0 = ((size_t)(b * Lseq + q0 + row)) * Dmod + h * HD + col;
                size_t o1 = o0 + 8 * Dmod;
                uint32_t lo0, lo1;
                uint32_t hi0 = packsplit(f0, f1, lo0);
                uint32_t hi1 = packsplit(f2, f3, lo1);
                *(uint32_t*)(Chi + o0) = hi0;
                *(uint32_t*)(Clo + o0) = lo0;
                *(uint32_t*)(Chi + o1) = hi1;
                *(uint32_t*)(Clo + o1) = lo1;
            }
        }
    }
}

// ============================================================
extern "C" void kernel_launch(void* const* d_in, const int* in_sizes, int n_in,
                              void* d_out, int out_size)
{
    const float* X  = (const float*)d_in[0];
    const float* Wq = (const float*)d_in[1];
    const float* Wk = (const float*)d_in[2];
    const float* Wv = (const float*)d_in[3];
    const float* Wo = (const float*)d_in[4];
    const float* bt = (const float*)d_in[5];
    float* out = (float*)d_out;

    void *pXhi, *pXlo, *pWhi, *pWlo, *pQhi, *pQlo, *pKhi, *pKlo,
         *pVthi, *pVtlo, *pChi, *pClo, *pF, *pHL, *pO;
    cudaGetSymbolAddress(&pXhi, g_Xhi);   cudaGetSymbolAddress(&pXlo, g_Xlo);
    cudaGetSymbolAddress(&pWhi, g_Whi);   cudaGetSymbolAddress(&pWlo, g_Wlo);
    cudaGetSymbolAddress(&pQhi, g_Qhi);   cudaGetSymbolAddress(&pQlo, g_Qlo);
    cudaGetSymbolAddress(&pKhi, g_Khi);   cudaGetSymbolAddress(&pKlo, g_Klo);
    cudaGetSymbolAddress(&pVthi, g_Vthi); cudaGetSymbolAddress(&pVtlo, g_Vtlo);
    cudaGetSymbolAddress(&pChi, g_Chi);   cudaGetSymbolAddress(&pClo, g_Clo);
    cudaGetSymbolAddress(&pF, g_F);
    cudaGetSymbolAddress(&pHL, g_HL);     cudaGetSymbolAddress(&pO, g_O);

    bf16 *Xhi = (bf16*)pXhi, *Xlo = (bf16*)pXlo;
    bf16 *Whi = (bf16*)pWhi, *Wlo = (bf16*)pWlo;
    bf16 *Qhi = (bf16*)pQhi, *Qlo = (bf16*)pQlo;
    bf16 *Khi = (bf16*)pKhi, *Klo = (bf16*)pKlo;
    bf16 *Vthi = (bf16*)pVthi, *Vtlo = (bf16*)pVtlo;
    bf16 *Chi = (bf16*)pChi, *Clo = (bf16*)pClo;
    float *Fb = (float*)pF, *HL = (float*)pHL, *Ob = (float*)pO;

    float* outp = Ob;
    float* pbp  = nullptr;
    long long osz = (long long)out_size;
    if (osz >= (long long)OUT_ELEMS + (long long)BIAS_ELEMS) {
        outp = out; pbp = out + (osz - (long long)BIAS_ELEMS);
    } else if (osz == (long long)BIAS_ELEMS) {
        pbp = out;
    } else if (osz >= (long long)OUT_ELEMS) {
        outp = out;
    }

    cudaFuncSetAttribute(flash_kernel, cudaFuncAttributeMaxDynamicSharedMemorySize, FLASH_SMEM);
    cudaFuncSetAttribute(qkv_kernel, cudaFuncAttributeMaxDynamicSharedMemorySize, GEMM_SMEM);
    cudaFuncSetAttribute(out_kernel, cudaFuncAttributeMaxDynamicSharedMemorySize, GEMM_SMEM);

    build_headlut_kernel<<<(Hh * 4095 + 255) / 256, 256>>>(bt, HL);                         // 1
    split_kernel<<<(OUT_ELEMS + 255) / 256, 256>>>(X, Xhi, Xlo, OUT_ELEMS);                 // 2
    splitW_kernel<<<dim3((Dmod * Dmod) / 256, 1, 4), 256>>>(Wq, Wk, Wv, Wo, Whi, Wlo);      // 3
    qkv_kernel<<<dim3(8, 32, 3), 128, GEMM_SMEM>>>(Xhi, Xlo, Whi, Wlo,
                                                   Qhi, Qlo, Khi, Klo, Fb);                 // 4
    v_packT_kernel<<<dim3(Lseq / 32, HD / 32, BH), dim3(32, 8)>>>(Fb, Vthi, Vtlo);          // 5
    flash_kernel<<<dim3(Lseq / 128, BH, pbp ? 2 : 1), 512, FLASH_SMEM>>>(
        Qhi, Qlo, Khi, Klo, Vthi, Vtlo, HL, pbp, Chi, Clo);                                 // 6
    out_kernel<<<dim3(8, 32), 128, GEMM_SMEM>>>(Chi, Clo, Whi + 3 * (Dmod * Dmod),
                                                Wlo + 3 * (Dmod * Dmod), outp);             // 7
}

// round 15
// speedup vs baseline: 1.1519x; 1.0197x over previous
#include <cuda_runtime.h>
#include <cuda_bf16.h>
#include <math.h>
#include <stdint.h>

#define Bsz   2
#define Lseq  2048
#define Dmod  1024
#define Hh    16
#define HD    64
#define MROWS 4096
#define BH    32
#define OUT_ELEMS  (MROWS * Dmod)
#define BIAS_ELEMS (Hh * Lseq * Lseq)
#define LOG2E 1.4426950408889634f

typedef __nv_bfloat16 bf16;

// ---------------- scratch ----------------
__device__ bf16 g_Xhi[MROWS * Dmod], g_Xlo[MROWS * Dmod];
__device__ bf16 g_Whi[4 * Dmod * Dmod], g_Wlo[4 * Dmod * Dmod];
__device__ bf16 g_Qhi[BH * Lseq * HD], g_Qlo[BH * Lseq * HD];
__device__ bf16 g_Khi[BH * Lseq * HD], g_Klo[BH * Lseq * HD];
__device__ bf16 g_Vhi[BH * Lseq * HD], g_Vlo[BH * Lseq * HD];   // [bh][l][d]
__device__ bf16 g_Chi[MROWS * Dmod], g_Clo[MROWS * Dmod];
__device__ float g_HL[Hh * 4095];
__device__ float g_O[OUT_ELEMS];

// ============================================================
// helpers
// ============================================================
__device__ __forceinline__ uint32_t smem_u32(const void* p) {
    uint32_t a;
    asm("{ .reg .u64 t; cvta.to.shared.u64 t, %1; cvt.u32.u64 %0, t; }" : "=r"(a) : "l"(p));
    return a;
}
__device__ __forceinline__ void ldsm4(uint32_t* r, uint32_t addr) {
    asm volatile("ldmatrix.sync.aligned.m8n8.x4.shared.b16 {%0,%1,%2,%3}, [%4];"
        : "=r"(r[0]), "=r"(r[1]), "=r"(r[2]), "=r"(r[3]) : "r"(addr));
}
__device__ __forceinline__ void ldsm4t(uint32_t* r, uint32_t addr) {
    asm volatile("ldmatrix.sync.aligned.m8n8.x4.trans.shared.b16 {%0,%1,%2,%3}, [%4];"
        : "=r"(r[0]), "=r"(r[1]), "=r"(r[2]), "=r"(r[3]) : "r"(addr));
}
__device__ __forceinline__ void mma_bf16(float* c, const uint32_t* a, const uint32_t* b) {
    asm volatile(
        "mma.sync.aligned.m16n8k16.row.col.f32.bf16.bf16.f32 "
        "{%0,%1,%2,%3}, {%4,%5,%6,%7}, {%8,%9}, {%0,%1,%2,%3};"
        : "+f"(c[0]), "+f"(c[1]), "+f"(c[2]), "+f"(c[3])
        : "r"(a[0]), "r"(a[1]), "r"(a[2]), "r"(a[3]), "r"(b[0]), "r"(b[1]));
}
__device__ __forceinline__ uint32_t packsplit(float x, float y, uint32_t& lo) {
    __nv_bfloat162 h = __floats2bfloat162_rn(x, y);
    float hx = __bfloat162float(h.x), hy = __bfloat162float(h.y);
    __nv_bfloat162 l = __floats2bfloat162_rn(x - hx, y - hy);
    lo = *(uint32_t*)&l;
    return *(uint32_t*)&h;
}
__device__ __forceinline__ void cpa16(uint32_t s, const void* g) {
    asm volatile("cp.async.cg.shared.global [%0], [%1], 16;" :: "r"(s), "l"(g) : "memory");
}
__device__ __forceinline__ void cpa_commit() { asm volatile("cp.async.commit_group;" ::: "memory"); }
__device__ __forceinline__ void cpa_wait0()  { asm volatile("cp.async.wait_group 0;" ::: "memory"); }

// ============================================================
// T5 bias LUT (verified)
// ============================================================
__global__ void build_headlut_kernel(const float* __restrict__ bt, float* __restrict__ hl)
{
    int idx = blockIdx.x * blockDim.x + threadIdx.x;
    if (idx >= Hh * 4095) return;
    int h = idx / 4095;
    int t = idx - h * 4095;
    int rel = t - 2047;
    int bucket = (rel > 0) ? 16 : 0;
    int rp = rel < 0 ? -rel : rel;
    int add;
    if (rp < 8) {
        add = rp;
    } else {
        float v = (logf((float)rp * 0.125f) / 2.772588722239781f) * 8.0f;
        int lv = 8 + (int)v;
        if (rp == 16) lv = 10;
        else if (rp == 32) lv = 12;
        else if (rp == 64) lv = 14;
        add = lv > 15 ? 15 : lv;
    }
    bucket += add;
    hl[idx] = bt[bucket * Hh + h];
}

// ============================================================
// splits: z=0..3 -> X quarters; z=4..7 -> W0..W3
// ============================================================
__device__ __forceinline__ void split1(float x, bf16& h, bf16& l) {
    h = __float2bfloat16(x);
    l = __float2bfloat16(x - __bfloat162float(h));
}

__global__ void splitAll_kernel(const float* __restrict__ X,
                                const float* __restrict__ W0, const float* __restrict__ W1,
                                const float* __restrict__ W2, const float* __restrict__ W3,
                                bf16* __restrict__ Xhi, bf16* __restrict__ Xlo,
                                bf16* __restrict__ Whi, bf16* __restrict__ Wlo)
{
    int z = blockIdx.z;
    int i = blockIdx.x * 256 + threadIdx.x;   // 0 .. 1048575
    const int Q = Dmod * Dmod;                // 1048576
    if (z < 4) {
        size_t o = (size_t)z * Q + i;
        split1(X[o], Xhi[o], Xlo[o]);
    } else {
        const float* s = (z == 4) ? W0 : (z == 5) ? W1 : (z == 6) ? W2 : W3;
        size_t o = (size_t)(z - 4) * Q + i;
        split1(s[i], Whi[o], Wlo[o]);
    }
}

// ============================================================
// 128-thread split-bf16 HMMA GEMM (verified R12)
// ============================================================
#define PITCH 40
#define TILEB (128 * PITCH * 2)
#define GEMM_SMEM (2 * 4 * TILEB)

__device__ __forceinline__ void hg_mainloop(
    const bf16* __restrict__ Abh, const bf16* __restrict__ Abl,
    const bf16* __restrict__ Bbh, const bf16* __restrict__ Bbl,
    float c[4][8][4], char* smraw)
{
    int tid = threadIdx.x, lane = tid & 31, wid = tid >> 5;
    int wm = wid >> 1, wn = wid & 1;
    uint32_t sb = smem_u32(smraw);

    int lrow = tid >> 2, lseg = tid & 3;

    uint32_t aOff[4], bOff[4];
#pragma unroll
    for (int im = 0; im < 4; ++im)
        aOff[im] = (uint32_t)(((wm * 64 + im * 16 + (lane & 15)) * PITCH + ((lane >> 4) << 3)) * 2);
    int kq = (lane & 8) ? 8 : 0;
#pragma unroll
    for (int p = 0; p < 4; ++p)
        bOff[p] = (uint32_t)(((wn * 64 + p * 16 + ((lane & 16) >> 1) + (lane & 7)) * PITCH + kq) * 2);

#pragma unroll
    for (int v = 0; v < 4; ++v) {
        int row = lrow + v * 32;
        uint32_t st = sb + (uint32_t)(row * PITCH * 2 + lseg * 16);
        size_t goff = (size_t)row * Dmod + lseg * 8;
        cpa16(st,             Abh + goff);
        cpa16(st + TILEB,     Abl + goff);
        cpa16(st + 2 * TILEB, Bbh + goff);
        cpa16(st + 3 * TILEB, Bbl + goff);
    }
    cpa_commit();

    for (int kc = 0; kc < 32; ++kc) {
        cpa_wait0();
        __syncthreads();
        if (kc < 31) {
            int k0 = (kc + 1) << 5;
            uint32_t stg = sb + ((kc + 1) & 1) * (4 * TILEB);
#pragma unroll
            for (int v = 0; v < 4; ++v) {
                int row = lrow + v * 32;
                uint32_t st = stg + (uint32_t)(row * PITCH * 2 + lseg * 16);
                size_t goff = (size_t)row * Dmod + k0 + lseg * 8;
                cpa16(st,             Abh + goff);
                cpa16(st + TILEB,     Abl + goff);
                cpa16(st + 2 * TILEB, Bbh + goff);
                cpa16(st + 3 * TILEB, Bbl + goff);
            }
            cpa_commit();
        }

        uint32_t stg = sb + (kc & 1) * (4 * TILEB);
#pragma unroll
        for (int ks = 0; ks < 32; ks += 16) {
            uint32_t aH[4][4], aL[4][4];
#pragma unroll
            for (int im = 0; im < 4; ++im) {
                ldsm4(aH[im], stg + aOff[im] + ks * 2);
                ldsm4(aL[im], stg + TILEB + aOff[im] + ks * 2);
            }
#pragma unroll
            for (int ph = 0; ph < 2; ++ph) {
                uint32_t bH[2][4], bL[2][4];
#pragma unroll
                for (int pp = 0; pp < 2; ++pp) {
                    int p = ph * 2 + pp;
                    ldsm4(bH[pp], stg + 2 * TILEB + bOff[p] + ks * 2);
                    ldsm4(bL[pp], stg + 3 * TILEB + bOff[p] + ks * 2);
                }
#pragma unroll
                for (int im = 0; im < 4; ++im)
#pragma unroll
                    for (int pp = 0; pp < 2; ++pp)
#pragma unroll
                        for (int nfl = 0; nfl < 2; ++nfl)
                            mma_bf16(c[im][ph * 4 + pp * 2 + nfl], aH[im], &bH[pp][nfl * 2]);
#pragma unroll
                for (int im = 0; im < 4; ++im)
#pragma unroll
                    for (int pp = 0; pp < 2; ++pp)
#pragma unroll
                        for (int nfl = 0; nfl < 2; ++nfl)
                            mma_bf16(c[im][ph * 4 + pp * 2 + nfl], aH[im], &bL[pp][nfl * 2]);
#pragma unroll
                for (int im = 0; im < 4; ++im)
#pragma unroll
                    for (int pp = 0; pp < 2; ++pp)
#pragma unroll
                        for (int nfl = 0; nfl < 2; ++nfl)
                            mma_bf16(c[im][ph * 4 + pp * 2 + nfl], aL[im], &bH[pp][nfl * 2]);
            }
        }
    }
}

// QKV: all three (z=0,1,2) pack hi/lo bf16 into per-head [bh][l][d]
__global__ void __launch_bounds__(128, 2) qkv_kernel(
    const bf16* __restrict__ Xhi, const bf16* __restrict__ Xlo,
    const bf16* __restrict__ Whi, const bf16* __restrict__ Wlo,
    bf16* __restrict__ Qhi, bf16* __restrict__ Qlo,
    bf16* __restrict__ Khi, bf16* __restrict__ Klo,
    bf16* __restrict__ Vhi, bf16* __restrict__ Vlo)
{
    extern __shared__ char smraw[];
    int z = blockIdx.z;
    int m0 = blockIdx.y << 7, n0 = blockIdx.x << 7;
    const size_t WSZ = (size_t)Dmod * Dmod;
    const bf16* Abh = Xhi + (size_t)m0 * Dmod;
    const bf16* Abl = Xlo + (size_t)m0 * Dmod;
    const bf16* Bbh = Whi + (size_t)z * WSZ + (size_t)n0 * Dmod;
    const bf16* Bbl = Wlo + (size_t)z * WSZ + (size_t)n0 * Dmod;

    float c[4][8][4];
#pragma unroll
    for (int im = 0; im < 4; ++im)
#pragma unroll
        for (int nf = 0; nf < 8; ++nf)
#pragma unroll
            for (int e = 0; e < 4; ++e) c[im][nf][e] = 0.f;

    hg_mainloop(Abh, Abl, Bbh, Bbl, c, smraw);

    int lane = threadIdx.x & 31, wid = threadIdx.x >> 5;
    int wm = wid >> 1, wn = wid & 1;
    bf16* Dhi = (z == 0) ? Qhi : (z == 1) ? Khi : Vhi;
    bf16* Dlo = (z == 0) ? Qlo : (z == 1) ? Klo : Vlo;

#pragma unroll
    for (int im = 0; im < 4; ++im) {
#pragma unroll
        for (int nf = 0; nf < 8; ++nf) {
            int row = m0 + wm * 64 + im * 16 + (lane >> 2);
            int col = n0 + wn * 64 + nf * 8 + 2 * (lane & 3);
            int b = row >> 11, h = col >> 6, d = col & 63;
            size_t o0 = (((size_t)(b * Hh + h)) * Lseq + (row & 2047)) * HD + d;
            size_t o1 = o0 + 8 * HD;
            uint32_t lo0, lo1;
            uint32_t hi0 = packsplit(c[im][nf][0], c[im][nf][1], lo0);
            uint32_t hi1 = packsplit(c[im][nf][2], c[im][nf][3], lo1);
            *(uint32_t*)(Dhi + o0) = hi0;
            *(uint32_t*)(Dlo + o0) = lo0;
            *(uint32_t*)(Dhi + o1) = hi1;
            *(uint32_t*)(Dlo + o1) = lo1;
        }
    }
}

__global__ void __launch_bounds__(128, 2) out_kernel(
    const bf16* __restrict__ Chi, const bf16* __restrict__ Clo,
    const bf16* __restrict__ Whi, const bf16* __restrict__ Wlo,
    float* __restrict__ outF)
{
    extern __shared__ char smraw[];
    int m0 = blockIdx.y << 7, n0 = blockIdx.x << 7;
    const bf16* Abh = Chi + (size_t)m0 * Dmod;
    const bf16* Abl = Clo + (size_t)m0 * Dmod;
    const bf16* Bbh = Whi + (size_t)n0 * Dmod;
    const bf16* Bbl = Wlo + (size_t)n0 * Dmod;

    float c[4][8][4];
#pragma unroll
    for (int im = 0; im < 4; ++im)
#pragma unroll
        for (int nf = 0; nf < 8; ++nf)
#pragma unroll
            for (int e = 0; e < 4; ++e) c[im][nf][e] = 0.f;

    hg_mainloop(Abh, Abl, Bbh, Bbl, c, smraw);

    int lane = threadIdx.x & 31, wid = threadIdx.x >> 5;
    int wm = wid >> 1, wn = wid & 1;
#pragma unroll
    for (int im = 0; im < 4; ++im) {
#pragma unroll
        for (int nf = 0; nf < 8; ++nf) {
            int row = m0 + wm * 64 + im * 16 + (lane >> 2);
            int col = n0 + wn * 64 + nf * 8 + 2 * (lane & 3);
            *(float2*)(outF + (size_t)row * Dmod + col)       = make_float2(c[im][nf][0], c[im][nf][1]);
            *(float2*)(outF + (size_t)(row + 8) * Dmod + col) = make_float2(c[im][nf][2], c[im][nf][3]);
        }
    }
}

// ============================================================
// Flash attention: V in [j][d] via ldmatrix.trans (R13 mapping,
// exonerated by bit-identical-rel_err evidence); per-warp softmax;
// one barrier/tile; bias fill fused (grid.z==1).
// ============================================================
#define QP 72
#define KTILE (128 * QP * 2)
#define F_QH 0
#define F_QL (F_QH + KTILE)
#define F_K  (F_QL + KTILE)
#define F_V  (F_K + 2 * 2 * KTILE)
#define F_WIN (F_V + 2 * 2 * KTILE)
#define F_PM  (F_WIN + 2048)
#define F_PS  (F_PM + 2048)
#define FLASH_SMEM (F_PS + 2048)

__global__ void __launch_bounds__(512, 1) flash_kernel(
    const bf16* __restrict__ Qhi, const bf16* __restrict__ Qlo,
    const bf16* __restrict__ Khi, const bf16* __restrict__ Klo,
    const bf16* __restrict__ Vhi, const bf16* __restrict__ Vlo,
    const float* __restrict__ hl, float* __restrict__ pb,
    bf16* __restrict__ Chi, bf16* __restrict__ Clo)
{
    if (blockIdx.z == 1) {
        int bb = blockIdx.y * (int)gridDim.x + blockIdx.x;
        int tid = threadIdx.x;
        int j = tid * 4;
#pragma unroll 4
        for (int rr = 0; rr < 64; ++rr) {
            int row = bb * 64 + rr;
            int hh = row >> 11, ii = row & 2047;
            const float* src = hl + hh * 4095 + (2047 - ii);
            float4* dst = (float4*)(pb + (size_t)row * Lseq);
            dst[tid] = make_float4(src[j], src[j + 1], src[j + 2], src[j + 3]);
        }
        return;
    }

    extern __shared__ char smc[];
    bf16* sQh = (bf16*)(smc + F_QH);
    bf16* sQl = (bf16*)(smc + F_QL);
    float* win = (float*)(smc + F_WIN);
    float* pm  = (float*)(smc + F_PM);
    float* ps  = (float*)(smc + F_PS);
    float* obuf = (float*)(smc + F_K);   // aliases K stage 0 (last tile kt=15 uses stage 1)

    int tid = threadIdx.x, lane = tid & 31, wid = tid >> 5;
    int wm = wid >> 2, wn = wid & 3;
    int q0 = blockIdx.x << 7;
    int bh = blockIdx.y;
    int h = bh & 15, b = bh >> 4;
    const bf16* Qbh = Qhi + (size_t)bh * Lseq * HD;
    const bf16* Qbl = Qlo + (size_t)bh * Lseq * HD;
    const bf16* Kbh = Khi + (size_t)bh * Lseq * HD;
    const bf16* Kbl = Klo + (size_t)bh * Lseq * HD;
    const bf16* Vbh = Vhi + (size_t)bh * Lseq * HD;
    const bf16* Vbl = Vlo + (size_t)bh * Lseq * HD;
    const float* hlh = hl + h * 4095;

    uint32_t sbase = smem_u32(smc);

    auto issue_tile = [&](int kt) {
        int k0 = kt << 7;
        uint32_t kst = sbase + F_K + (kt & 1) * (2 * KTILE);
        uint32_t vst = sbase + F_V + (kt & 1) * (2 * KTILE);
#pragma unroll
        for (int v = 0; v < 2; ++v) {
            int idx = v * 512 + tid;
            int row = idx >> 3, seg = idx & 7;
            size_t g = (size_t)(k0 + row) * HD + seg * 8;
            uint32_t s = row * QP * 2 + seg * 16;
            cpa16(kst + s,         Kbh + g);
            cpa16(kst + KTILE + s, Kbl + g);
            cpa16(vst + s,         Vbh + g);
            cpa16(vst + KTILE + s, Vbl + g);
        }
        cpa_commit();
        if (tid < 255) win[(kt & 1) * 256 + tid] = hlh[k0 - q0 + 1920 + tid];
    };

    issue_tile(0);

#pragma unroll
    for (int v = 0; v < 2; ++v) {
        int idx = v * 512 + tid;
        int row = idx >> 3, seg = idx & 7;
        *(uint4*)(sQh + row * QP + seg * 8) = *(const uint4*)(Qbh + (size_t)(q0 + row) * HD + seg * 8);
        *(uint4*)(sQl + row * QP + seg * 8) = *(const uint4*)(Qbl + (size_t)(q0 + row) * HD + seg * 8);
    }

    uint32_t sQh32 = smem_u32(sQh), sQl32 = smem_u32(sQl);

    uint32_t qOff[2], kOff[2], vOffT[4];
#pragma unroll
    for (int im = 0; im < 2; ++im)
        qOff[im] = (uint32_t)(((wm * 32 + im * 16 + (lane & 15)) * QP + ((lane >> 4) << 3)) * 2);
    int kq = (lane & 8) ? 8 : 0;
#pragma unroll
    for (int p = 0; p < 2; ++p)
        kOff[p] = (uint32_t)(((wn * 32 + p * 16 + ((lane & 16) >> 1) + (lane & 7)) * QP + kq) * 2);
#pragma unroll
    for (int p = 0; p < 4; ++p)
        vOffT[p] = (uint32_t)(((wn * 32 + (lane & 15)) * QP + p * 16 + ((lane >> 4) << 3)) * 2);

    int rbase = wm * 32 + (lane >> 2);
    int cbase = wn * 32 + 2 * (lane & 3);

    float O[2][8][4];
    float rm[2][2], rl[2][2];
#pragma unroll
    for (int im = 0; im < 2; ++im) {
        rm[im][0] = -1e30f; rm[im][1] = -1e30f;
        rl[im][0] = 0.f;    rl[im][1] = 0.f;
#pragma unroll
        for (int nf = 0; nf < 8; ++nf)
#pragma unroll
            for (int e = 0; e < 4; ++e) O[im][nf][e] = 0.f;
    }

    for (int kt = 0; kt < Lseq / 128; ++kt) {
        cpa_wait0();
        __syncthreads();
        if (kt < Lseq / 128 - 1) issue_tile(kt + 1);

        uint32_t kb = sbase + F_K + (kt & 1) * (2 * KTILE);
        uint32_t vb = sbase + F_V + (kt & 1) * (2 * KTILE);
        const float* winc = win + (kt & 1) * 256;

        float c[2][4][4];
#pragma unroll
        for (int im = 0; im < 2; ++im)
#pragma unroll
            for (int nf = 0; nf < 4; ++nf)
#pragma unroll
                for (int e = 0; e < 4; ++e) c[im][nf][e] = 0.f;
#pragma unroll
        for (int ks = 0; ks < 64; ks += 16) {
            uint32_t aH[2][4], aL[2][4], bH[2][4], bL[2][4];
#pragma unroll
            for (int im = 0; im < 2; ++im) {
                ldsm4(aH[im], sQh32 + qOff[im] + ks * 2);
                ldsm4(aL[im], sQl32 + qOff[im] + ks * 2);
            }
#pragma unroll
            for (int p = 0; p < 2; ++p) {
                ldsm4(bH[p], kb + kOff[p] + ks * 2);
                ldsm4(bL[p], kb + KTILE + kOff[p] + ks * 2);
            }
#pragma unroll
            for (int im = 0; im < 2; ++im)
#pragma unroll
                for (int nf = 0; nf < 4; ++nf)
                    mma_bf16(c[im][nf], aH[im], &bH[nf >> 1][(nf & 1) * 2]);
#pragma unroll
            for (int im = 0; im < 2; ++im)
#pragma unroll
                for (int nf = 0; nf < 4; ++nf)
                    mma_bf16(c[im][nf], aH[im], &bL[nf >> 1][(nf & 1) * 2]);
#pragma unroll
            for (int im = 0; im < 2; ++im)
#pragma unroll
                for (int nf = 0; nf < 4; ++nf)
                    mma_bf16(c[im][nf], aL[im], &bH[nf >> 1][(nf & 1) * 2]);
        }

#pragma unroll
        for (int im = 0; im < 2; ++im) {
            int row = rbase + im * 16;
            float ma = -1e30f, mb = -1e30f;
#pragma unroll
            for (int nf = 0; nf < 4; ++nf) {
                int idx = cbase + nf * 8 - row + 127;
                c[im][nf][0] += winc[idx];
                c[im][nf][1] += winc[idx + 1];
                c[im][nf][2] += winc[idx - 8];
                c[im][nf][3] += winc[idx - 7];
                ma = fmaxf(ma, fmaxf(c[im][nf][0], c[im][nf][1]));
                mb = fmaxf(mb, fmaxf(c[im][nf][2], c[im][nf][3]));
            }
            ma = fmaxf(ma, __shfl_xor_sync(0xffffffffu, ma, 1));
            ma = fmaxf(ma, __shfl_xor_sync(0xffffffffu, ma, 2));
            mb = fmaxf(mb, __shfl_xor_sync(0xffffffffu, mb, 1));
            mb = fmaxf(mb, __shfl_xor_sync(0xffffffffu, mb, 2));
            float mn0 = fmaxf(rm[im][0], ma);
            float mn1 = fmaxf(rm[im][1], mb);
            float a0 = exp2f((rm[im][0] - mn0) * LOG2E);
            float a1 = exp2f((rm[im][1] - mn1) * LOG2E);
            rm[im][0] = mn0; rm[im][1] = mn1;

            float sa = 0.f, sb = 0.f;
#pragma unroll
            for (int nf = 0; nf < 4; ++nf) {
                c[im][nf][0] = exp2f((c[im][nf][0] - mn0) * LOG2E);
                c[im][nf][1] = exp2f((c[im][nf][1] - mn0) * LOG2E);
                c[im][nf][2] = exp2f((c[im][nf][2] - mn1) * LOG2E);
                c[im][nf][3] = exp2f((c[im][nf][3] - mn1) * LOG2E);
                sa += c[im][nf][0] + c[im][nf][1];
                sb += c[im][nf][2] + c[im][nf][3];
            }
            sa += __shfl_xor_sync(0xffffffffu, sa, 1);
            sa += __shfl_xor_sync(0xffffffffu, sa, 2);
            sb += __shfl_xor_sync(0xffffffffu, sb, 1);
            sb += __shfl_xor_sync(0xffffffffu, sb, 2);
            rl[im][0] = rl[im][0] * a0 + sa;
            rl[im][1] = rl[im][1] * a1 + sb;

#pragma unroll
            for (int nf = 0; nf < 8; ++nf) {
                O[im][nf][0] *= a0; O[im][nf][1] *= a0;
                O[im][nf][2] *= a1; O[im][nf][3] *= a1;
            }
        }

        uint32_t aPh[2][2][4], aPl[2][2][4];
#pragma unroll
        for (int kp = 0; kp < 2; ++kp)
#pragma unroll
            for (int im = 0; im < 2; ++im) {
                aPh[kp][im][0] = packsplit(c[im][2 * kp][0],     c[im][2 * kp][1],     aPl[kp][im][0]);
                aPh[kp][im][1] = packsplit(c[im][2 * kp][2],     c[im][2 * kp][3],     aPl[kp][im][1]);
                aPh[kp][im][2] = packsplit(c[im][2 * kp + 1][0], c[im][2 * kp + 1][1], aPl[kp][im][2]);
                aPh[kp][im][3] = packsplit(c[im][2 * kp + 1][2], c[im][2 * kp + 1][3], aPl[kp][im][3]);
            }
#pragma unroll
        for (int p = 0; p < 4; ++p) {
            uint32_t vH[2][4], vL[2][4];
#pragma unroll
            for (int kp = 0; kp < 2; ++kp) {
                uint32_t off = vOffT[p] + kp * 16 * QP * 2;   // +16 j-rows
                ldsm4t(vH[kp], vb + off);
                ldsm4t(vL[kp], vb + KTILE + off);
            }
#pragma unroll
            for (int kp = 0; kp < 2; ++kp)
#pragma unroll
                for (int im = 0; im < 2; ++im)
#pragma unroll
                    for (int nfl = 0; nfl < 2; ++nfl)
                        mma_bf16(O[im][p * 2 + nfl], aPh[kp][im], &vH[kp][nfl * 2]);
#pragma unroll
            for (int kp = 0; kp < 2; ++kp)
#pragma unroll
                for (int im = 0; im < 2; ++im)
#pragma unroll
                    for (int nfl = 0; nfl < 2; ++nfl)
                        mma_bf16(O[im][p * 2 + nfl], aPl[kp][im], &vH[kp][nfl * 2]);
#pragma unroll
            for (int kp = 0; kp < 2; ++kp)
#pragma unroll
                for (int im = 0; im < 2; ++im)
#pragma unroll
                    for (int nfl = 0; nfl < 2; ++nfl)
                        mma_bf16(O[im][p * 2 + nfl], aPh[kp][im], &vL[kp][nfl * 2]);
        }
    }

    // ---- merge warp quadrants ----
#pragma unroll
    for (int im = 0; im < 2; ++im)
#pragma unroll
        for (int hf = 0; hf < 2; ++hf)
            if ((lane & 3) == 0)
                pm[(rbase + im * 16 + hf * 8) * 4 + wn] = rm[im][hf];
    __syncthreads();
#pragma unroll
    for (int im = 0; im < 2; ++im) {
#pragma unroll
        for (int hf = 0; hf < 2; ++hf) {
            int row = rbase + im * 16 + hf * 8;
            float mg = fmaxf(fmaxf(pm[row * 4], pm[row * 4 + 1]),
                             fmaxf(pm[row * 4 + 2], pm[row * 4 + 3]));
            float sw = exp2f((rm[im][hf] - mg) * LOG2E);
#pragma unroll
            for (int nf = 0; nf < 8; ++nf) {
                O[im][nf][hf * 2]     *= sw;
                O[im][nf][hf * 2 + 1] *= sw;
            }
            if ((lane & 3) == 0) ps[row * 4 + wn] = rl[im][hf] * sw;
        }
    }
    __syncthreads();

    int colb = 2 * (lane & 3);
    if (wn == 3) {
#pragma unroll
        for (int im = 0; im < 2; ++im) {
            int row = rbase + im * 16;
#pragma unroll
            for (int nf = 0; nf < 8; ++nf) {
                int col = nf * 8 + colb;
                *(float2*)(obuf + row * 64 + col)       = make_float2(O[im][nf][0], O[im][nf][1]);
                *(float2*)(obuf + (row + 8) * 64 + col) = make_float2(O[im][nf][2], O[im][nf][3]);
            }
        }
    }
    __syncthreads();
    if (wn == 2) {
#pragma unroll
        for (int im = 0; im < 2; ++im) {
            int row = rbase + im * 16;
#pragma unroll
            for (int nf = 0; nf < 8; ++nf) {
                int col = nf * 8 + colb;
                float2 t0 = *(float2*)(obuf + row * 64 + col);
                float2 t1 = *(float2*)(obuf + (row + 8) * 64 + col);
                *(float2*)(obuf + row * 64 + col)       = make_float2(t0.x + O[im][nf][0], t0.y + O[im][nf][1]);
                *(float2*)(obuf + (row + 8) * 64 + col) = make_float2(t1.x + O[im][nf][2], t1.y + O[im][nf][3]);
            }
        }
    }
    __syncthreads();
    if (wn == 1) {
#pragma unroll
        for (int im = 0; im < 2; ++im) {
            int row = rbase + im * 16;
#pragma unroll
            for (int nf = 0; nf < 8; ++nf) {
                int col = nf * 8 + colb;
                float2 t0 = *(float2*)(obuf + row * 64 + col);
                float2 t1 = *(float2*)(obuf + (row + 8) * 64 + col);
                *(float2*)(obuf + row * 64 + col)       = make_float2(t0.x + O[im][nf][0], t0.y + O[im][nf][1]);
                *(float2*)(obuf + (row + 8) * 64 + col) = make_float2(t1.x + O[im][nf][2], t1.y + O[im][nf][3]);
            }
        }
    }
    __syncthreads();
    if (wn == 0) {
#pragma unroll
        for (int im = 0; im < 2; ++im) {
            int row = rbase + im * 16;
            float l0 = ps[row * 4] + ps[row * 4 + 1] + ps[row * 4 + 2] + ps[row * 4 + 3];
            int row8 = row + 8;
            float l1 = ps[row8 * 4] + ps[row8 * 4 + 1] + ps[row8 * 4 + 2] + ps[row8 * 4 + 3];
            float inv = 1.f / l0, inv8 = 1.f / l1;
#pragma unroll
            for (int nf = 0; nf < 8; ++nf) {
                int col = nf * 8 + colb;
                float2 t0 = *(float2*)(obuf + row * 64 + col);
                float2 t1 = *(float2*)(obuf + (row + 8) * 64 + col);
                float f0 = (O[im][nf][0] + t0.x) * inv;
                float f1 = (O[im][nf][1] + t0.y) * inv;
                float f2 = (O[im][nf][2] + t1.x) * inv8;
                float f3 = (O[im][nf][3] + t1.y) * inv8;
                size_t o0 = ((size_t)(b * Lseq + q0 + row)) * Dmod + h * HD + col;
                size_t o1 = o0 + 8 * Dmod;
                uint32_t lo0, lo1;
                uint32_t hi0 = packsplit(f0, f1, lo0);
                uint32_t hi1 = packsplit(f2, f3, lo1);
                *(uint32_t*)(Chi + o0) = hi0;
                *(uint32_t*)(Clo + o0) = lo0;
                *(uint32_t*)(Chi + o1) = hi1;
                *(uint32_t*)(Clo + o1) = lo1;
            }
        }
    }
}

// ============================================================
extern "C" void kernel_launch(void* const* d_in, const int* in_sizes, int n_in,
                              void* d_out, int out_size)
{
    const float* X  = (const float*)d_in[0];
    const float* Wq = (const float*)d_in[1];
    const float* Wk = (const float*)d_in[2];
    const float* Wv = (const float*)d_in[3];
    const float* Wo = (const float*)d_in[4];
    const float* bt = (const float*)d_in[5];
    float* out = (float*)d_out;

    void *pXhi, *pXlo, *pWhi, *pWlo, *pQhi, *pQlo, *pKhi, *pKlo,
         *pVhi, *pVlo, *pChi, *pClo, *pHL, *pO;
    cudaGetSymbolAddress(&pXhi, g_Xhi);   cudaGetSymbolAddress(&pXlo, g_Xlo);
    cudaGetSymbolAddress(&pWhi, g_Whi);   cudaGetSymbolAddress(&pWlo, g_Wlo);
    cudaGetSymbolAddress(&pQhi, g_Qhi);   cudaGetSymbolAddress(&pQlo, g_Qlo);
    cudaGetSymbolAddress(&pKhi, g_Khi);   cudaGetSymbolAddress(&pKlo, g_Klo);
    cudaGetSymbolAddress(&pVhi, g_Vhi);   cudaGetSymbolAddress(&pVlo, g_Vlo);
    cudaGetSymbolAddress(&pChi, g_Chi);   cudaGetSymbolAddress(&pClo, g_Clo);
    cudaGetSymbolAddress(&pHL, g_HL);     cudaGetSymbolAddress(&pO, g_O);

    bf16 *Xhi = (bf16*)pXhi, *Xlo = (bf16*)pXlo;
    bf16 *Whi = (bf16*)pWhi, *Wlo = (bf16*)pWlo;
    bf16 *Qhi = (bf16*)pQhi, *Qlo = (bf16*)pQlo;
    bf16 *Khi = (bf16*)pKhi, *Klo = (bf16*)pKlo;
    bf16 *Vhi = (bf16*)pVhi, *Vlo = (bf16*)pVlo;
    bf16 *Chi = (bf16*)pChi, *Clo = (bf16*)pClo;
    float *HL = (float*)pHL, *Ob = (float*)pO;

    float* outp = Ob;
    float* pbp  = nullptr;
    long long osz = (long long)out_size;
    if (osz >= (long long)OUT_ELEMS + (long long)BIAS_ELEMS) {
        outp = out; pbp = out + (osz - (long long)BIAS_ELEMS);
    } else if (osz == (long long)BIAS_ELEMS) {
        pbp = out;
    } else if (osz >= (long long)OUT_ELEMS) {
        outp = out;
    }

    cudaFuncSetAttribute(flash_kernel, cudaFuncAttributeMaxDynamicSharedMemorySize, FLASH_SMEM);
    cudaFuncSetAttribute(qkv_kernel, cudaFuncAttributeMaxDynamicSharedMemorySize, GEMM_SMEM);
    cudaFuncSetAttribute(out_kernel, cudaFuncAttributeMaxDynamicSharedMemorySize, GEMM_SMEM);

    build_headlut_kernel<<<(Hh * 4095 + 255) / 256, 256>>>(bt, HL);                         // 1
    splitAll_kernel<<<dim3((Dmod * Dmod) / 256, 1, 8), 256>>>(
        X, Wq, Wk, Wv, Wo, Xhi, Xlo, Whi, Wlo);                                             // 2
    qkv_kernel<<<dim3(8, 32, 3), 128, GEMM_SMEM>>>(Xhi, Xlo, Whi, Wlo,
                                                   Qhi, Qlo, Khi, Klo, Vhi, Vlo);           // 3
    flash_kernel<<<dim3(Lseq / 128, BH, pbp ? 2 : 1), 512, FLASH_SMEM>>>(
        Qhi, Qlo, Khi, Klo, Vhi, Vlo, HL, pbp, Chi, Clo);                                   // 4 (profiled)
    out_kernel<<<dim3(8, 32), 128, GEMM_SMEM>>>(Chi, Clo, Whi + 3 * (Dmod * Dmod),
                                                Wlo + 3 * (Dmod * Dmod), outp);             // 5
}

// round 16
// speedup vs baseline: 1.1609x; 1.0078x over previous
#include <cuda_runtime.h>
#include <cuda_bf16.h>
#include <math.h>
#include <stdint.h>

#define Bsz   2
#define Lseq  2048
#define Dmod  1024
#define Hh    16
#define HD    64
#define MROWS 4096
#define BH    32
#define OUT_ELEMS  (MROWS * Dmod)
#define BIAS_ELEMS (Hh * Lseq * Lseq)
#define LOG2E 1.4426950408889634f

typedef __nv_bfloat16 bf16;

// ---------------- scratch ----------------
__device__ bf16 g_Xhi[MROWS * Dmod], g_Xlo[MROWS * Dmod];
__device__ bf16 g_Whi[4 * Dmod * Dmod], g_Wlo[4 * Dmod * Dmod];
__device__ bf16 g_Qhi[BH * Lseq * HD], g_Qlo[BH * Lseq * HD];
__device__ bf16 g_Khi[BH * Lseq * HD], g_Klo[BH * Lseq * HD];
__device__ bf16 g_Vhi[BH * Lseq * HD], g_Vlo[BH * Lseq * HD];   // [bh][l][d]
__device__ bf16 g_Chi[MROWS * Dmod], g_Clo[MROWS * Dmod];
__device__ float g_HL[Hh * 4095];
__device__ float g_O[OUT_ELEMS];

// ============================================================
// helpers
// ============================================================
__device__ __forceinline__ uint32_t smem_u32(const void* p) {
    uint32_t a;
    asm("{ .reg .u64 t; cvta.to.shared.u64 t, %1; cvt.u32.u64 %0, t; }" : "=r"(a) : "l"(p));
    return a;
}
__device__ __forceinline__ void ldsm4(uint32_t* r, uint32_t addr) {
    asm volatile("ldmatrix.sync.aligned.m8n8.x4.shared.b16 {%0,%1,%2,%3}, [%4];"
        : "=r"(r[0]), "=r"(r[1]), "=r"(r[2]), "=r"(r[3]) : "r"(addr));
}
__device__ __forceinline__ void ldsm4t(uint32_t* r, uint32_t addr) {
    asm volatile("ldmatrix.sync.aligned.m8n8.x4.trans.shared.b16 {%0,%1,%2,%3}, [%4];"
        : "=r"(r[0]), "=r"(r[1]), "=r"(r[2]), "=r"(r[3]) : "r"(addr));
}
__device__ __forceinline__ void mma_bf16(float* c, const uint32_t* a, const uint32_t* b) {
    asm volatile(
        "mma.sync.aligned.m16n8k16.row.col.f32.bf16.bf16.f32 "
        "{%0,%1,%2,%3}, {%4,%5,%6,%7}, {%8,%9}, {%0,%1,%2,%3};"
        : "+f"(c[0]), "+f"(c[1]), "+f"(c[2]), "+f"(c[3])
        : "r"(a[0]), "r"(a[1]), "r"(a[2]), "r"(a[3]), "r"(b[0]), "r"(b[1]));
}
__device__ __forceinline__ uint32_t packsplit(float x, float y, uint32_t& lo) {
    __nv_bfloat162 h = __floats2bfloat162_rn(x, y);
    float hx = __bfloat162float(h.x), hy = __bfloat162float(h.y);
    __nv_bfloat162 l = __floats2bfloat162_rn(x - hx, y - hy);
    lo = *(uint32_t*)&l;
    return *(uint32_t*)&h;
}
__device__ __forceinline__ void cpa16(uint32_t s, const void* g) {
    asm volatile("cp.async.cg.shared.global [%0], [%1], 16;" :: "r"(s), "l"(g) : "memory");
}
__device__ __forceinline__ void cpa_commit() { asm volatile("cp.async.commit_group;" ::: "memory"); }
__device__ __forceinline__ void cpa_wait0()  { asm volatile("cp.async.wait_group 0;" ::: "memory"); }

// ============================================================
// T5 bias LUT (verified)
// ============================================================
__global__ void build_headlut_kernel(const float* __restrict__ bt, float* __restrict__ hl)
{
    int idx = blockIdx.x * blockDim.x + threadIdx.x;
    if (idx >= Hh * 4095) return;
    int h = idx / 4095;
    int t = idx - h * 4095;
    int rel = t - 2047;
    int bucket = (rel > 0) ? 16 : 0;
    int rp = rel < 0 ? -rel : rel;
    int add;
    if (rp < 8) {
        add = rp;
    } else {
        float v = (logf((float)rp * 0.125f) / 2.772588722239781f) * 8.0f;
        int lv = 8 + (int)v;
        if (rp == 16) lv = 10;
        else if (rp == 32) lv = 12;
        else if (rp == 64) lv = 14;
        add = lv > 15 ? 15 : lv;
    }
    bucket += add;
    hl[idx] = bt[bucket * Hh + h];
}

// ============================================================
// splits: z=0..3 -> X quarters; z=4..7 -> W0..W3 (verified R15)
// ============================================================
__device__ __forceinline__ void split1(float x, bf16& h, bf16& l) {
    h = __float2bfloat16(x);
    l = __float2bfloat16(x - __bfloat162float(h));
}

__global__ void splitAll_kernel(const float* __restrict__ X,
                                const float* __restrict__ W0, const float* __restrict__ W1,
                                const float* __restrict__ W2, const float* __restrict__ W3,
                                bf16* __restrict__ Xhi, bf16* __restrict__ Xlo,
                                bf16* __restrict__ Whi, bf16* __restrict__ Wlo)
{
    int z = blockIdx.z;
    int i = blockIdx.x * 256 + threadIdx.x;
    const int Q = Dmod * Dmod;
    if (z < 4) {
        size_t o = (size_t)z * Q + i;
        split1(X[o], Xhi[o], Xlo[o]);
    } else {
        const float* s = (z == 4) ? W0 : (z == 5) ? W1 : (z == 6) ? W2 : W3;
        size_t o = (size_t)(z - 4) * Q + i;
        split1(s[i], Whi[o], Wlo[o]);
    }
}

// ============================================================
// 128-thread split-bf16 HMMA GEMM (verified R12)
// ============================================================
#define PITCH 40
#define TILEB (128 * PITCH * 2)
#define GEMM_SMEM (2 * 4 * TILEB)

__device__ __forceinline__ void hg_mainloop(
    const bf16* __restrict__ Abh, const bf16* __restrict__ Abl,
    const bf16* __restrict__ Bbh, const bf16* __restrict__ Bbl,
    float c[4][8][4], char* smraw)
{
    int tid = threadIdx.x, lane = tid & 31, wid = tid >> 5;
    int wm = wid >> 1, wn = wid & 1;
    uint32_t sb = smem_u32(smraw);

    int lrow = tid >> 2, lseg = tid & 3;

    uint32_t aOff[4], bOff[4];
#pragma unroll
    for (int im = 0; im < 4; ++im)
        aOff[im] = (uint32_t)(((wm * 64 + im * 16 + (lane & 15)) * PITCH + ((lane >> 4) << 3)) * 2);
    int kq = (lane & 8) ? 8 : 0;
#pragma unroll
    for (int p = 0; p < 4; ++p)
        bOff[p] = (uint32_t)(((wn * 64 + p * 16 + ((lane & 16) >> 1) + (lane & 7)) * PITCH + kq) * 2);

#pragma unroll
    for (int v = 0; v < 4; ++v) {
        int row = lrow + v * 32;
        uint32_t st = sb + (uint32_t)(row * PITCH * 2 + lseg * 16);
        size_t goff = (size_t)row * Dmod + lseg * 8;
        cpa16(st,             Abh + goff);
        cpa16(st + TILEB,     Abl + goff);
        cpa16(st + 2 * TILEB, Bbh + goff);
        cpa16(st + 3 * TILEB, Bbl + goff);
    }
    cpa_commit();

    for (int kc = 0; kc < 32; ++kc) {
        cpa_wait0();
        __syncthreads();
        if (kc < 31) {
            int k0 = (kc + 1) << 5;
            uint32_t stg = sb + ((kc + 1) & 1) * (4 * TILEB);
#pragma unroll
            for (int v = 0; v < 4; ++v) {
                int row = lrow + v * 32;
                uint32_t st = stg + (uint32_t)(row * PITCH * 2 + lseg * 16);
                size_t goff = (size_t)row * Dmod + k0 + lseg * 8;
                cpa16(st,             Abh + goff);
                cpa16(st + TILEB,     Abl + goff);
                cpa16(st + 2 * TILEB, Bbh + goff);
                cpa16(st + 3 * TILEB, Bbl + goff);
            }
            cpa_commit();
        }

        uint32_t stg = sb + (kc & 1) * (4 * TILEB);
#pragma unroll
        for (int ks = 0; ks < 32; ks += 16) {
            uint32_t aH[4][4], aL[4][4];
#pragma unroll
            for (int im = 0; im < 4; ++im) {
                ldsm4(aH[im], stg + aOff[im] + ks * 2);
                ldsm4(aL[im], stg + TILEB + aOff[im] + ks * 2);
            }
#pragma unroll
            for (int ph = 0; ph < 2; ++ph) {
                uint32_t bH[2][4], bL[2][4];
#pragma unroll
                for (int pp = 0; pp < 2; ++pp) {
                    int p = ph * 2 + pp;
                    ldsm4(bH[pp], stg + 2 * TILEB + bOff[p] + ks * 2);
                    ldsm4(bL[pp], stg + 3 * TILEB + bOff[p] + ks * 2);
                }
#pragma unroll
                for (int im = 0; im < 4; ++im)
#pragma unroll
                    for (int pp = 0; pp < 2; ++pp)
#pragma unroll
                        for (int nfl = 0; nfl < 2; ++nfl)
                            mma_bf16(c[im][ph * 4 + pp * 2 + nfl], aH[im], &bH[pp][nfl * 2]);
#pragma unroll
                for (int im = 0; im < 4; ++im)
#pragma unroll
                    for (int pp = 0; pp < 2; ++pp)
#pragma unroll
                        for (int nfl = 0; nfl < 2; ++nfl)
                            mma_bf16(c[im][ph * 4 + pp * 2 + nfl], aH[im], &bL[pp][nfl * 2]);
#pragma unroll
                for (int im = 0; im < 4; ++im)
#pragma unroll
                    for (int pp = 0; pp < 2; ++pp)
#pragma unroll
                        for (int nfl = 0; nfl < 2; ++nfl)
                            mma_bf16(c[im][ph * 4 + pp * 2 + nfl], aL[im], &bH[pp][nfl * 2]);
            }
        }
    }
}

// QKV: all three (z=0,1,2) pack hi/lo bf16 into per-head [bh][l][d]
__global__ void __launch_bounds__(128, 2) qkv_kernel(
    const bf16* __restrict__ Xhi, const bf16* __restrict__ Xlo,
    const bf16* __restrict__ Whi, const bf16* __restrict__ Wlo,
    bf16* __restrict__ Qhi, bf16* __restrict__ Qlo,
    bf16* __restrict__ Khi, bf16* __restrict__ Klo,
    bf16* __restrict__ Vhi, bf16* __restrict__ Vlo)
{
    extern __shared__ char smraw[];
    int z = blockIdx.z;
    int m0 = blockIdx.y << 7, n0 = blockIdx.x << 7;
    const size_t WSZ = (size_t)Dmod * Dmod;
    const bf16* Abh = Xhi + (size_t)m0 * Dmod;
    const bf16* Abl = Xlo + (size_t)m0 * Dmod;
    const bf16* Bbh = Whi + (size_t)z * WSZ + (size_t)n0 * Dmod;
    const bf16* Bbl = Wlo + (size_t)z * WSZ + (size_t)n0 * Dmod;

    float c[4][8][4];
#pragma unroll
    for (int im = 0; im < 4; ++im)
#pragma unroll
        for (int nf = 0; nf < 8; ++nf)
#pragma unroll
            for (int e = 0; e < 4; ++e) c[im][nf][e] = 0.f;

    hg_mainloop(Abh, Abl, Bbh, Bbl, c, smraw);

    int lane = threadIdx.x & 31, wid = threadIdx.x >> 5;
    int wm = wid >> 1, wn = wid & 1;
    bf16* Dhi = (z == 0) ? Qhi : (z == 1) ? Khi : Vhi;
    bf16* Dlo = (z == 0) ? Qlo : (z == 1) ? Klo : Vlo;

#pragma unroll
    for (int im = 0; im < 4; ++im) {
#pragma unroll
        for (int nf = 0; nf < 8; ++nf) {
            int row = m0 + wm * 64 + im * 16 + (lane >> 2);
            int col = n0 + wn * 64 + nf * 8 + 2 * (lane & 3);
            int b = row >> 11, h = col >> 6, d = col & 63;
            size_t o0 = (((size_t)(b * Hh + h)) * Lseq + (row & 2047)) * HD + d;
            size_t o1 = o0 + 8 * HD;
            uint32_t lo0, lo1;
            uint32_t hi0 = packsplit(c[im][nf][0], c[im][nf][1], lo0);
            uint32_t hi1 = packsplit(c[im][nf][2], c[im][nf][3], lo1);
            *(uint32_t*)(Dhi + o0) = hi0;
            *(uint32_t*)(Dlo + o0) = lo0;
            *(uint32_t*)(Dhi + o1) = hi1;
            *(uint32_t*)(Dlo + o1) = lo1;
        }
    }
}

__global__ void __launch_bounds__(128, 2) out_kernel(
    const bf16* __restrict__ Chi, const bf16* __restrict__ Clo,
    const bf16* __restrict__ Whi, const bf16* __restrict__ Wlo,
    float* __restrict__ outF)
{
    extern __shared__ char smraw[];
    int m0 = blockIdx.y << 7, n0 = blockIdx.x << 7;
    const bf16* Abh = Chi + (size_t)m0 * Dmod;
    const bf16* Abl = Clo + (size_t)m0 * Dmod;
    const bf16* Bbh = Whi + (size_t)n0 * Dmod;
    const bf16* Bbl = Wlo + (size_t)n0 * Dmod;

    float c[4][8][4];
#pragma unroll
    for (int im = 0; im < 4; ++im)
#pragma unroll
        for (int nf = 0; nf < 8; ++nf)
#pragma unroll
            for (int e = 0; e < 4; ++e) c[im][nf][e] = 0.f;

    hg_mainloop(Abh, Abl, Bbh, Bbl, c, smraw);

    int lane = threadIdx.x & 31, wid = threadIdx.x >> 5;
    int wm = wid >> 1, wn = wid & 1;
#pragma unroll
    for (int im = 0; im < 4; ++im) {
#pragma unroll
        for (int nf = 0; nf < 8; ++nf) {
            int row = m0 + wm * 64 + im * 16 + (lane >> 2);
            int col = n0 + wn * 64 + nf * 8 + 2 * (lane & 3);
            *(float2*)(outF + (size_t)row * Dmod + col)       = make_float2(c[im][nf][0], c[im][nf][1]);
            *(float2*)(outF + (size_t)(row + 8) * Dmod + col) = make_float2(c[im][nf][2], c[im][nf][3]);
        }
    }
}

// ============================================================
// Flash attention (R15, verified): PV restructured kp-outer to cut
// live registers (P-pack fragments for one kp at a time).
// ============================================================
#define QP 72
#define KTILE (128 * QP * 2)
#define F_QH 0
#define F_QL (F_QH + KTILE)
#define F_K  (F_QL + KTILE)
#define F_V  (F_K + 2 * 2 * KTILE)
#define F_WIN (F_V + 2 * 2 * KTILE)
#define F_PM  (F_WIN + 2048)
#define F_PS  (F_PM + 2048)
#define FLASH_SMEM (F_PS + 2048)

__global__ void __launch_bounds__(512, 1) flash_kernel(
    const bf16* __restrict__ Qhi, const bf16* __restrict__ Qlo,
    const bf16* __restrict__ Khi, const bf16* __restrict__ Klo,
    const bf16* __restrict__ Vhi, const bf16* __restrict__ Vlo,
    const float* __restrict__ hl, float* __restrict__ pb,
    bf16* __restrict__ Chi, bf16* __restrict__ Clo)
{
    if (blockIdx.z == 1) {
        int bb = blockIdx.y * (int)gridDim.x + blockIdx.x;
        int tid = threadIdx.x;
        int j = tid * 4;
#pragma unroll 4
        for (int rr = 0; rr < 64; ++rr) {
            int row = bb * 64 + rr;
            int hh = row >> 11, ii = row & 2047;
            const float* src = hl + hh * 4095 + (2047 - ii);
            float4* dst = (float4*)(pb + (size_t)row * Lseq);
            dst[tid] = make_float4(src[j], src[j + 1], src[j + 2], src[j + 3]);
        }
        return;
    }

    extern __shared__ char smc[];
    bf16* sQh = (bf16*)(smc + F_QH);
    bf16* sQl = (bf16*)(smc + F_QL);
    float* win = (float*)(smc + F_WIN);
    float* pm  = (float*)(smc + F_PM);
    float* ps  = (float*)(smc + F_PS);
    float* obuf = (float*)(smc + F_K);

    int tid = threadIdx.x, lane = tid & 31, wid = tid >> 5;
    int wm = wid >> 2, wn = wid & 3;
    int q0 = blockIdx.x << 7;
    int bh = blockIdx.y;
    int h = bh & 15, b = bh >> 4;
    const bf16* Qbh = Qhi + (size_t)bh * Lseq * HD;
    const bf16* Qbl = Qlo + (size_t)bh * Lseq * HD;
    const bf16* Kbh = Khi + (size_t)bh * Lseq * HD;
    const bf16* Kbl = Klo + (size_t)bh * Lseq * HD;
    const bf16* Vbh = Vhi + (size_t)bh * Lseq * HD;
    const bf16* Vbl = Vlo + (size_t)bh * Lseq * HD;
    const float* hlh = hl + h * 4095;

    uint32_t sbase = smem_u32(smc);

    auto issue_tile = [&](int kt) {
        int k0 = kt << 7;
        uint32_t kst = sbase + F_K + (kt & 1) * (2 * KTILE);
        uint32_t vst = sbase + F_V + (kt & 1) * (2 * KTILE);
#pragma unroll
        for (int v = 0; v < 2; ++v) {
            int idx = v * 512 + tid;
            int row = idx >> 3, seg = idx & 7;
            size_t g = (size_t)(k0 + row) * HD + seg * 8;
            uint32_t s = row * QP * 2 + seg * 16;
            cpa16(kst + s,         Kbh + g);
            cpa16(kst + KTILE + s, Kbl + g);
            cpa16(vst + s,         Vbh + g);
            cpa16(vst + KTILE + s, Vbl + g);
        }
        cpa_commit();
        if (tid < 255) win[(kt & 1) * 256 + tid] = hlh[k0 - q0 + 1920 + tid];
    };

    issue_tile(0);

#pragma unroll
    for (int v = 0; v < 2; ++v) {
        int idx = v * 512 + tid;
        int row = idx >> 3, seg = idx & 7;
        *(uint4*)(sQh + row * QP + seg * 8) = *(const uint4*)(Qbh + (size_t)(q0 + row) * HD + seg * 8);
        *(uint4*)(sQl + row * QP + seg * 8) = *(const uint4*)(Qbl + (size_t)(q0 + row) * HD + seg * 8);
    }

    uint32_t sQh32 = smem_u32(sQh), sQl32 = smem_u32(sQl);

    uint32_t qOff[2], kOff[2], vOffT[4];
#pragma unroll
    for (int im = 0; im < 2; ++im)
        qOff[im] = (uint32_t)(((wm * 32 + im * 16 + (lane & 15)) * QP + ((lane >> 4) << 3)) * 2);
    int kq = (lane & 8) ? 8 : 0;
#pragma unroll
    for (int p = 0; p < 2; ++p)
        kOff[p] = (uint32_t)(((wn * 32 + p * 16 + ((lane & 16) >> 1) + (lane & 7)) * QP + kq) * 2);
#pragma unroll
    for (int p = 0; p < 4; ++p)
        vOffT[p] = (uint32_t)(((wn * 32 + (lane & 15)) * QP + p * 16 + ((lane >> 4) << 3)) * 2);

    int rbase = wm * 32 + (lane >> 2);
    int cbase = wn * 32 + 2 * (lane & 3);

    float O[2][8][4];
    float rm[2][2], rl[2][2];
#pragma unroll
    for (int im = 0; im < 2; ++im) {
        rm[im][0] = -1e30f; rm[im][1] = -1e30f;
        rl[im][0] = 0.f;    rl[im][1] = 0.f;
#pragma unroll
        for (int nf = 0; nf < 8; ++nf)
#pragma unroll
            for (int e = 0; e < 4; ++e) O[im][nf][e] = 0.f;
    }

    for (int kt = 0; kt < Lseq / 128; ++kt) {
        cpa_wait0();
        __syncthreads();
        if (kt < Lseq / 128 - 1) issue_tile(kt + 1);

        uint32_t kb = sbase + F_K + (kt & 1) * (2 * KTILE);
        uint32_t vb = sbase + F_V + (kt & 1) * (2 * KTILE);
        const float* winc = win + (kt & 1) * 256;

        float c[2][4][4];
#pragma unroll
        for (int im = 0; im < 2; ++im)
#pragma unroll
            for (int nf = 0; nf < 4; ++nf)
#pragma unroll
                for (int e = 0; e < 4; ++e) c[im][nf][e] = 0.f;
#pragma unroll
        for (int ks = 0; ks < 64; ks += 16) {
            uint32_t aH[2][4], aL[2][4], bH[2][4], bL[2][4];
#pragma unroll
            for (int im = 0; im < 2; ++im) {
                ldsm4(aH[im], sQh32 + qOff[im] + ks * 2);
                ldsm4(aL[im], sQl32 + qOff[im] + ks * 2);
            }
#pragma unroll
            for (int p = 0; p < 2; ++p) {
                ldsm4(bH[p], kb + kOff[p] + ks * 2);
                ldsm4(bL[p], kb + KTILE + kOff[p] + ks * 2);
            }
#pragma unroll
            for (int im = 0; im < 2; ++im)
#pragma unroll
                for (int nf = 0; nf < 4; ++nf)
                    mma_bf16(c[im][nf], aH[im], &bH[nf >> 1][(nf & 1) * 2]);
#pragma unroll
            for (int im = 0; im < 2; ++im)
#pragma unroll
                for (int nf = 0; nf < 4; ++nf)
                    mma_bf16(c[im][nf], aH[im], &bL[nf >> 1][(nf & 1) * 2]);
#pragma unroll
            for (int im = 0; im < 2; ++im)
#pragma unroll
                for (int nf = 0; nf < 4; ++nf)
                    mma_bf16(c[im][nf], aL[im], &bH[nf >> 1][(nf & 1) * 2]);
        }

#pragma unroll
        for (int im = 0; im < 2; ++im) {
            int row = rbase + im * 16;
            float ma = -1e30f, mb = -1e30f;
#pragma unroll
            for (int nf = 0; nf < 4; ++nf) {
                int idx = cbase + nf * 8 - row + 127;
                c[im][nf][0] += winc[idx];
                c[im][nf][1] += winc[idx + 1];
                c[im][nf][2] += winc[idx - 8];
                c[im][nf][3] += winc[idx - 7];
                ma = fmaxf(ma, fmaxf(c[im][nf][0], c[im][nf][1]));
                mb = fmaxf(mb, fmaxf(c[im][nf][2], c[im][nf][3]));
            }
            ma = fmaxf(ma, __shfl_xor_sync(0xffffffffu, ma, 1));
            ma = fmaxf(ma, __shfl_xor_sync(0xffffffffu, ma, 2));
            mb = fmaxf(mb, __shfl_xor_sync(0xffffffffu, mb, 1));
            mb = fmaxf(mb, __shfl_xor_sync(0xffffffffu, mb, 2));
            float mn0 = fmaxf(rm[im][0], ma);
            float mn1 = fmaxf(rm[im][1], mb);
            float a0 = exp2f((rm[im][0] - mn0) * LOG2E);
            float a1 = exp2f((rm[im][1] - mn1) * LOG2E);
            rm[im][0] = mn0; rm[im][1] = mn1;

            float sa = 0.f, sb = 0.f;
#pragma unroll
            for (int nf = 0; nf < 4; ++nf) {
                c[im][nf][0] = exp2f((c[im][nf][0] - mn0) * LOG2E);
                c[im][nf][1] = exp2f((c[im][nf][1] - mn0) * LOG2E);
                c[im][nf][2] = exp2f((c[im][nf][2] - mn1) * LOG2E);
                c[im][nf][3] = exp2f((c[im][nf][3] - mn1) * LOG2E);
                sa += c[im][nf][0] + c[im][nf][1];
                sb += c[im][nf][2] + c[im][nf][3];
            }
            sa += __shfl_xor_sync(0xffffffffu, sa, 1);
            sa += __shfl_xor_sync(0xffffffffu, sa, 2);
            sb += __shfl_xor_sync(0xffffffffu, sb, 1);
            sb += __shfl_xor_sync(0xffffffffu, sb, 2);
            rl[im][0] = rl[im][0] * a0 + sa;
            rl[im][1] = rl[im][1] * a1 + sb;

#pragma unroll
            for (int nf = 0; nf < 8; ++nf) {
                O[im][nf][0] *= a0; O[im][nf][1] *= a0;
                O[im][nf][2] *= a1; O[im][nf][3] *= a1;
            }
        }

        // ---- PV: kp outer; pack P for one kp at a time (reg relief) ----
#pragma unroll
        for (int kp = 0; kp < 2; ++kp) {
            uint32_t aPh[2][4], aPl[2][4];
#pragma unroll
            for (int im = 0; im < 2; ++im) {
                aPh[im][0] = packsplit(c[im][2 * kp][0],     c[im][2 * kp][1],     aPl[im][0]);
                aPh[im][1] = packsplit(c[im][2 * kp][2],     c[im][2 * kp][3],     aPl[im][1]);
                aPh[im][2] = packsplit(c[im][2 * kp + 1][0], c[im][2 * kp + 1][1], aPl[im][2]);
                aPh[im][3] = packsplit(c[im][2 * kp + 1][2], c[im][2 * kp + 1][3], aPl[im][3]);
            }
#pragma unroll
            for (int p = 0; p < 4; ++p) {
                uint32_t vH[4], vL[4];
                uint32_t off = vOffT[p] + kp * 16 * QP * 2;
                ldsm4t(vH, vb + off);
                ldsm4t(vL, vb + KTILE + off);
#pragma unroll
                for (int im = 0; im < 2; ++im)
#pragma unroll
                    for (int nfl = 0; nfl < 2; ++nfl)
                        mma_bf16(O[im][p * 2 + nfl], aPh[im], &vH[nfl * 2]);
#pragma unroll
                for (int im = 0; im < 2; ++im)
#pragma unroll
                    for (int nfl = 0; nfl < 2; ++nfl)
                        mma_bf16(O[im][p * 2 + nfl], aPl[im], &vH[nfl * 2]);
#pragma unroll
                for (int im = 0; im < 2; ++im)
#pragma unroll
                    for (int nfl = 0; nfl < 2; ++nfl)
                        mma_bf16(O[im][p * 2 + nfl], aPh[im], &vL[nfl * 2]);
            }
        }
    }

    // ---- merge warp quadrants ----
#pragma unroll
    for (int im = 0; im < 2; ++im)
#pragma unroll
        for (int hf = 0; hf < 2; ++hf)
            if ((lane & 3) == 0)
                pm[(rbase + im * 16 + hf * 8) * 4 + wn] = rm[im][hf];
    __syncthreads();
#pragma unroll
    for (int im = 0; im < 2; ++im) {
#pragma unroll
        for (int hf = 0; hf < 2; ++hf) {
            int row = rbase + im * 16 + hf * 8;
            float mg = fmaxf(fmaxf(pm[row * 4], pm[row * 4 + 1]),
                             fmaxf(pm[row * 4 + 2], pm[row * 4 + 3]));
            float sw = exp2f((rm[im][hf] - mg) * LOG2E);
#pragma unroll
            for (int nf = 0; nf < 8; ++nf) {
                O[im][nf][hf * 2]     *= sw;
                O[im][nf][hf * 2 + 1] *= sw;
            }
            if ((lane & 3) == 0) ps[row * 4 + wn] = rl[im][hf] * sw;
        }
    }
    __syncthreads();

    int colb = 2 * (lane & 3);
    if (wn == 3) {
#pragma unroll
        for (int im = 0; im < 2; ++im) {
            int row = rbase + im * 16;
#pragma unroll
            for (int nf = 0; nf < 8; ++nf) {
                int col = nf * 8 + colb;
                *(float2*)(obuf + row * 64 + col)       = make_float2(O[im][nf][0], O[im][nf][1]);
                *(float2*)(obuf + (row + 8) * 64 + col) = make_float2(O[im][nf][2], O[im][nf][3]);
            }
        }
    }
    __syncthreads();
    if (wn == 2) {
#pragma unroll
        for (int im = 0; im < 2; ++im) {
            int row = rbase + im * 16;
#pragma unroll
            for (int nf = 0; nf < 8; ++nf) {
                int col = nf * 8 + colb;
                float2 t0 = *(float2*)(obuf + row * 64 + col);
                float2 t1 = *(float2*)(obuf + (row + 8) * 64 + col);
                *(float2*)(obuf + row * 64 + col)       = make_float2(t0.x + O[im][nf][0], t0.y + O[im][nf][1]);
                *(float2*)(obuf + (row + 8) * 64 + col) = make_float2(t1.x + O[im][nf][2], t1.y + O[im][nf][3]);
            }
        }
    }
    __syncthreads();
    if (wn == 1) {
#pragma unroll
        for (int im = 0; im < 2; ++im) {
            int row = rbase + im * 16;
#pragma unroll
            for (int nf = 0; nf < 8; ++nf) {
                int col = nf * 8 + colb;
                float2 t0 = *(float2*)(obuf + row * 64 + col);
                float2 t1 = *(float2*)(obuf + (row + 8) * 64 + col);
                *(float2*)(obuf + row * 64 + col)       = make_float2(t0.x + O[im][nf][0], t0.y + O[im][nf][1]);
                *(float2*)(obuf + (row + 8) * 64 + col) = make_float2(t1.x + O[im][nf][2], t1.y + O[im][nf][3]);
            }
        }
    }
    __syncthreads();
    if (wn == 0) {
#pragma unroll
        for (int im = 0; im < 2; ++im) {
            int row = rbase + im * 16;
            float l0 = ps[row * 4] + ps[row * 4 + 1] + ps[row * 4 + 2] + ps[row * 4 + 3];
            int row8 = row + 8;
            float l1 = ps[row8 * 4] + ps[row8 * 4 + 1] + ps[row8 * 4 + 2] + ps[row8 * 4 + 3];
            float inv = 1.f / l0, inv8 = 1.f / l1;
#pragma unroll
            for (int nf = 0; nf < 8; ++nf) {
                int col = nf * 8 + colb;
                float2 t0 = *(float2*)(obuf + row * 64 + col);
                float2 t1 = *(float2*)(obuf + (row + 8) * 64 + col);
                float f0 = (O[im][nf][0] + t0.x) * inv;
                float f1 = (O[im][nf][1] + t0.y) * inv;
                float f2 = (O[im][nf][2] + t1.x) * inv8;
                float f3 = (O[im][nf][3] + t1.y) * inv8;
                size_t o0 = ((size_t)(b * Lseq + q0 + row)) * Dmod + h * HD + col;
                size_t o1 = o0 + 8 * Dmod;
                uint32_t lo0, lo1;
                uint32_t hi0 = packsplit(f0, f1, lo0);
                uint32_t hi1 = packsplit(f2, f3, lo1);
                *(uint32_t*)(Chi + o0) = hi0;
                *(uint32_t*)(Clo + o0) = lo0;
                *(uint32_t*)(Chi + o1) = hi1;
                *(uint32_t*)(Clo + o1) = lo1;
            }
        }
    }
}

// ============================================================
extern "C" void kernel_launch(void* const* d_in, const int* in_sizes, int n_in,
                              void* d_out, int out_size)
{
    const float* X  = (const float*)d_in[0];
    const float* Wq = (const float*)d_in[1];
    const float* Wk = (const float*)d_in[2];
    const float* Wv = (const float*)d_in[3];
    const float* Wo = (const float*)d_in[4];
    const float* bt = (const float*)d_in[5];
    float* out = (float*)d_out;

    void *pXhi, *pXlo, *pWhi, *pWlo, *pQhi, *pQlo, *pKhi, *pKlo,
         *pVhi, *pVlo, *pChi, *pClo, *pHL, *pO;
    cudaGetSymbolAddress(&pXhi, g_Xhi);   cudaGetSymbolAddress(&pXlo, g_Xlo);
    cudaGetSymbolAddress(&pWhi, g_Whi);   cudaGetSymbolAddress(&pWlo, g_Wlo);
    cudaGetSymbolAddress(&pQhi, g_Qhi);   cudaGetSymbolAddress(&pQlo, g_Qlo);
    cudaGetSymbolAddress(&pKhi, g_Khi);   cudaGetSymbolAddress(&pKlo, g_Klo);
    cudaGetSymbolAddress(&pVhi, g_Vhi);   cudaGetSymbolAddress(&pVlo, g_Vlo);
    cudaGetSymbolAddress(&pChi, g_Chi);   cudaGetSymbolAddress(&pClo, g_Clo);
    cudaGetSymbolAddress(&pHL, g_HL);     cudaGetSymbolAddress(&pO, g_O);

    bf16 *Xhi = (bf16*)pXhi, *Xlo = (bf16*)pXlo;
    bf16 *Whi = (bf16*)pWhi, *Wlo = (bf16*)pWlo;
    bf16 *Qhi = (bf16*)pQhi, *Qlo = (bf16*)pQlo;
    bf16 *Khi = (bf16*)pKhi, *Klo = (bf16*)pKlo;
    bf16 *Vhi = (bf16*)pVhi, *Vlo = (bf16*)pVlo;
    bf16 *Chi = (bf16*)pChi, *Clo = (bf16*)pClo;
    float *HL = (float*)pHL, *Ob = (float*)pO;

    float* outp = Ob;
    float* pbp  = nullptr;
    long long osz = (long long)out_size;
    if (osz >= (long long)OUT_ELEMS + (long long)BIAS_ELEMS) {
        outp = out; pbp = out + (osz - (long long)BIAS_ELEMS);
    } else if (osz == (long long)BIAS_ELEMS) {
        pbp = out;
    } else if (osz >= (long long)OUT_ELEMS) {
        outp = out;
    }

    cudaFuncSetAttribute(flash_kernel, cudaFuncAttributeMaxDynamicSharedMemorySize, FLASH_SMEM);
    cudaFuncSetAttribute(qkv_kernel, cudaFuncAttributeMaxDynamicSharedMemorySize, GEMM_SMEM);
    cudaFuncSetAttribute(out_kernel, cudaFuncAttributeMaxDynamicSharedMemorySize, GEMM_SMEM);

    build_headlut_kernel<<<(Hh * 4095 + 255) / 256, 256>>>(bt, HL);                         // 1
    splitAll_kernel<<<dim3((Dmod * Dmod) / 256, 1, 8), 256>>>(
        X, Wq, Wk, Wv, Wo, Xhi, Xlo, Whi, Wlo);                                             // 2
    qkv_kernel<<<dim3(8, 32, 3), 128, GEMM_SMEM>>>(Xhi, Xlo, Whi, Wlo,
                                                   Qhi, Qlo, Khi, Klo, Vhi, Vlo);           // 3
    flash_kernel<<<dim3(Lseq / 128, BH, pbp ? 2 : 1), 512, FLASH_SMEM>>>(
        Qhi, Qlo, Khi, Klo, Vhi, Vlo, HL, pbp, Chi, Clo);                                   // 4 (profiled)
    out_kernel<<<dim3(8, 32), 128, GEMM_SMEM>>>(Chi, Clo, Whi + 3 * (Dmod * Dmod),
                                                Wlo + 3 * (Dmod * Dmod), outp);             // 5
}